// round 5
// baseline (speedup 1.0000x reference)
#include <cuda_runtime.h>
#include <math.h>

#define Nn 20000
#define IN_DIMc 1536
#define HIDc 256
#define HEADSc 4
#define HDc 64
#define HOPSc 3
#define NCLSc 3
#define EMAXc 400000
#define EPSV 1e-5f
#define NEG_SLOPE 0.2f

// ---------------- scratch (device globals; no allocations) ----------------
__device__ float g_X[Nn * HIDc];
__device__ float g_tmp[Nn * HIDc];
__device__ float g_XL[Nn * HIDc];
__device__ float g_XR[Nn * HIDc];
__device__ float g_logits[(EMAXc + Nn) * HEADSc];
__device__ float g_m[Nn * HEADSc];
__device__ float g_denom[Nn * HEADSc];
__device__ float g_gout[Nn * HIDc];
__device__ int g_flag;  // 1 = edge_index is int64, 0 = int32

// ---------------- utilities ----------------
__device__ __forceinline__ void atomicMaxF(float* addr, float v) {
    int old = __float_as_int(*addr);
    while (v > __int_as_float(old)) {
        int assumed = old;
        old = atomicCAS((int*)addr, assumed, __float_as_int(v));
        if (old == assumed) break;
    }
}

__global__ void detect_idx_kernel(const void* __restrict__ ei) {
    if (threadIdx.x == 0 && blockIdx.x == 0) {
        const long long* p = (const long long*)ei;
        int ok = 1;
        for (int i = 0; i < 256; i++) {
            long long v = p[i];
            if (v < 0 || v >= (long long)Nn) { ok = 0; break; }
        }
        g_flag = ok;
    }
}

__device__ __forceinline__ int edge_get(const void* ei, long long idx, int flag) {
    return flag ? (int)((const long long*)ei)[idx] : ((const int*)ei)[idx];
}

// ---------------- GEMM: C[M,Nc] = A[M,K] @ B[K,Nc] + bias ----------------
// BM=128, BN=128, BK=16, 256 threads, 8x8 micro-tile (2x2 of float4),
// register-prefetch pipelining. Requires Nc % 128 == 0 (always 256 here),
// K % 16 == 0. gridDim.z selects (B0,bias0,C0) vs (B1,bias1,C1) to fuse the
// Wl / Wr GEMM pair into one launch (shared A tiles stay L2-hot, tail halves).
__global__ __launch_bounds__(256, 2)
void gemm128_kernel(const float* __restrict__ A,
                    const float* __restrict__ B0, const float* __restrict__ B1,
                    const float* __restrict__ bias0, const float* __restrict__ bias1,
                    float* __restrict__ C0, float* __restrict__ C1,
                    int M, int K, int Nc) {
    const float* __restrict__ B = blockIdx.z ? B1 : B0;
    const float* __restrict__ bias = blockIdx.z ? bias1 : bias0;
    float* __restrict__ C = blockIdx.z ? C1 : C0;

    __shared__ float As[16][128];
    __shared__ float Bs[16][128];

    int tid = threadIdx.x;
    int tx = tid & 15, ty = tid >> 4;
    int rm = blockIdx.x * 128;
    int cn = blockIdx.y * 128;

    // A-load mapping: float4 index f in [0,512): row=f>>2 (0..127), q=f&3
    int af0 = tid, af1 = tid + 256;
    int ar0 = af0 >> 2, aq0 = (af0 & 3) * 4;
    int ar1 = af1 >> 2, aq1 = (af1 & 3) * 4;
    // B-load mapping: float4 index f: brow=f>>5 (0..15), bq=f&31
    int br0 = af0 >> 5, bq0 = (af0 & 31) * 4;
    int br1 = af1 >> 5, bq1 = (af1 & 31) * 4;

    const float* Arow0 = A + (long long)(rm + ar0) * K;
    const float* Arow1 = A + (long long)(rm + ar1) * K;
    bool av0ok = (rm + ar0) < M;
    bool av1ok = (rm + ar1) < M;

    float acc[2][2][4][4];
#pragma unroll
    for (int a = 0; a < 2; a++)
#pragma unroll
        for (int b = 0; b < 2; b++)
#pragma unroll
            for (int i = 0; i < 4; i++)
#pragma unroll
                for (int j = 0; j < 4; j++) acc[a][b][i][j] = 0.f;

    int nt = K / 16;
    float4 pa0, pa1, pb0, pb1;

    // prologue: fetch tile 0
    pa0 = av0ok ? *(const float4*)(Arow0 + aq0) : make_float4(0.f, 0.f, 0.f, 0.f);
    pa1 = av1ok ? *(const float4*)(Arow1 + aq1) : make_float4(0.f, 0.f, 0.f, 0.f);
    pb0 = *(const float4*)(B + (long long)br0 * Nc + cn + bq0);
    pb1 = *(const float4*)(B + (long long)br1 * Nc + cn + bq1);

    for (int t = 0; t < nt; t++) {
        // store prefetched tile into smem
        As[aq0 + 0][ar0] = pa0.x; As[aq0 + 1][ar0] = pa0.y;
        As[aq0 + 2][ar0] = pa0.z; As[aq0 + 3][ar0] = pa0.w;
        As[aq1 + 0][ar1] = pa1.x; As[aq1 + 1][ar1] = pa1.y;
        As[aq1 + 2][ar1] = pa1.z; As[aq1 + 3][ar1] = pa1.w;
        *(float4*)&Bs[br0][bq0] = pb0;
        *(float4*)&Bs[br1][bq1] = pb1;
        __syncthreads();

        // prefetch next tile (global loads overlap with compute below)
        if (t + 1 < nt) {
            int kt = (t + 1) * 16;
            pa0 = av0ok ? *(const float4*)(Arow0 + kt + aq0) : make_float4(0.f, 0.f, 0.f, 0.f);
            pa1 = av1ok ? *(const float4*)(Arow1 + kt + aq1) : make_float4(0.f, 0.f, 0.f, 0.f);
            pb0 = *(const float4*)(B + (long long)(kt + br0) * Nc + cn + bq0);
            pb1 = *(const float4*)(B + (long long)(kt + br1) * Nc + cn + bq1);
        }

#pragma unroll
        for (int k = 0; k < 16; k++) {
            float4 av[2], bv[2];
            av[0] = *(float4*)&As[k][ty * 4];
            av[1] = *(float4*)&As[k][ty * 4 + 64];
            bv[0] = *(float4*)&Bs[k][tx * 4];
            bv[1] = *(float4*)&Bs[k][tx * 4 + 64];
#pragma unroll
            for (int a = 0; a < 2; a++) {
                float ax = av[a].x, ay = av[a].y, az = av[a].z, aw = av[a].w;
#pragma unroll
                for (int b = 0; b < 2; b++) {
                    float bx = bv[b].x, by = bv[b].y, bz = bv[b].z, bw = bv[b].w;
                    acc[a][b][0][0] += ax * bx; acc[a][b][0][1] += ax * by;
                    acc[a][b][0][2] += ax * bz; acc[a][b][0][3] += ax * bw;
                    acc[a][b][1][0] += ay * bx; acc[a][b][1][1] += ay * by;
                    acc[a][b][1][2] += ay * bz; acc[a][b][1][3] += ay * bw;
                    acc[a][b][2][0] += az * bx; acc[a][b][2][1] += az * by;
                    acc[a][b][2][2] += az * bz; acc[a][b][2][3] += az * bw;
                    acc[a][b][3][0] += aw * bx; acc[a][b][3][1] += aw * by;
                    acc[a][b][3][2] += aw * bz; acc[a][b][3][3] += aw * bw;
                }
            }
        }
        __syncthreads();
    }

    // epilogue
    float4 bb0 = *(const float4*)(bias + cn + tx * 4);
    float4 bb1 = *(const float4*)(bias + cn + tx * 4 + 64);
#pragma unroll
    for (int a = 0; a < 2; a++) {
#pragma unroll
        for (int i = 0; i < 4; i++) {
            int row = rm + a * 64 + ty * 4 + i;
            if (row < M) {
                float4 o0, o1;
                o0.x = acc[a][0][i][0] + bb0.x; o0.y = acc[a][0][i][1] + bb0.y;
                o0.z = acc[a][0][i][2] + bb0.z; o0.w = acc[a][0][i][3] + bb0.w;
                o1.x = acc[a][1][i][0] + bb1.x; o1.y = acc[a][1][i][1] + bb1.y;
                o1.z = acc[a][1][i][2] + bb1.z; o1.w = acc[a][1][i][3] + bb1.w;
                *(float4*)(C + (long long)row * Nc + cn + tx * 4) = o0;
                *(float4*)(C + (long long)row * Nc + cn + tx * 4 + 64) = o1;
            }
        }
    }
}

// ---------------- block stats helper ----------------
__device__ __forceinline__ void block_mean_var_256(float v, float* smem, float& mu, float& var) {
    float s = v, sq = v * v;
#pragma unroll
    for (int o = 16; o > 0; o >>= 1) {
        s += __shfl_xor_sync(0xffffffffu, s, o);
        sq += __shfl_xor_sync(0xffffffffu, sq, o);
    }
    int w = threadIdx.x >> 5, l = threadIdx.x & 31;
    if (l == 0) { smem[w] = s; smem[8 + w] = sq; }
    __syncthreads();
    if (w == 0) {
        s = (l < 8) ? smem[l] : 0.f;
        sq = (l < 8) ? smem[8 + l] : 0.f;
#pragma unroll
        for (int o = 4; o > 0; o >>= 1) {
            s += __shfl_xor_sync(0xffffffffu, s, o);
            sq += __shfl_xor_sync(0xffffffffu, sq, o);
        }
        if (l == 0) { smem[0] = s; smem[8] = sq; }
    }
    __syncthreads();
    mu = smem[0] * (1.f / HIDc);
    var = smem[8] * (1.f / HIDc) - mu * mu;
}

__global__ void ln_kernel(const float* __restrict__ in, const float* __restrict__ g,
                          const float* __restrict__ b, float* __restrict__ out) {
    __shared__ float smem[16];
    int n = blockIdx.x, c = threadIdx.x;
    float v = in[(long long)n * HIDc + c];
    float mu, var;
    block_mean_var_256(v, smem, mu, var);
    out[(long long)n * HIDc + c] = (v - mu) * rsqrtf(var + EPSV) * g[c] + b[c];
}

// ---------------- per-hop segment buffers init ----------------
__global__ void init_seg_kernel() {
    int i = blockIdx.x * blockDim.x + threadIdx.x;
    if (i < Nn * HIDc) g_gout[i] = 0.f;
    if (i < Nn * HEADSc) { g_m[i] = -1e30f; g_denom[i] = 0.f; }
}

// ---------------- edge pass 1: logits + segment max ----------------
__global__ void edge_logits_kernel(const void* __restrict__ ei,
                                   const float* __restrict__ XL, const float* __restrict__ XR,
                                   const float* __restrict__ att,
                                   float* __restrict__ logits, float* __restrict__ m,
                                   int E, int etot) {
    int e = blockIdx.x * 8 + (threadIdx.x >> 5);
    if (e >= etot) return;
    int lane = threadIdx.x & 31;
    int flag = g_flag;
    int src, dst;
    if (e < E) {
        src = edge_get(ei, e, flag);
        dst = edge_get(ei, (long long)E + e, flag);
    } else {
        src = dst = e - E;
    }
    const float4* xl4 = (const float4*)(XL + (long long)src * HIDc);
    const float4* xr4 = (const float4*)(XR + (long long)dst * HIDc);
    int head = lane >> 3;
    float s = 0.f;
#pragma unroll
    for (int q = 0; q < 2; q++) {
        float4 a = xl4[lane * 2 + q];
        float4 b = xr4[lane * 2 + q];
        int cbase = lane * 8 + q * 4;
        const float* ap = att + head * HDc + (cbase & 63);
        float v;
        v = a.x + b.x; v = v > 0.f ? v : NEG_SLOPE * v; s += v * ap[0];
        v = a.y + b.y; v = v > 0.f ? v : NEG_SLOPE * v; s += v * ap[1];
        v = a.z + b.z; v = v > 0.f ? v : NEG_SLOPE * v; s += v * ap[2];
        v = a.w + b.w; v = v > 0.f ? v : NEG_SLOPE * v; s += v * ap[3];
    }
    s += __shfl_xor_sync(0xffffffffu, s, 1);
    s += __shfl_xor_sync(0xffffffffu, s, 2);
    s += __shfl_xor_sync(0xffffffffu, s, 4);
    if ((lane & 7) == 0) {
        logits[(long long)e * HEADSc + head] = s;
        atomicMaxF(&m[dst * HEADSc + head], s);
    }
}

// ---------------- edge pass 2: exp + denom + weighted scatter ----------------
__global__ void edge_scatter_kernel(const void* __restrict__ ei,
                                    const float* __restrict__ XL,
                                    const float* __restrict__ logits, const float* __restrict__ m,
                                    float* __restrict__ denom, float* __restrict__ gout,
                                    int E, int etot) {
    int e = blockIdx.x * 8 + (threadIdx.x >> 5);
    if (e >= etot) return;
    int lane = threadIdx.x & 31;
    int flag = g_flag;
    int src, dst;
    if (e < E) {
        src = edge_get(ei, e, flag);
        dst = edge_get(ei, (long long)E + e, flag);
    } else {
        src = dst = e - E;
    }
    float ex = 0.f;
    if (lane < HEADSc) {
        float lo = logits[(long long)e * HEADSc + lane];
        ex = __expf(lo - m[dst * HEADSc + lane]);
        atomicAdd(&denom[dst * HEADSc + lane], ex);
    }
    const float* xl = XL + (long long)src * HIDc;
    float* go = gout + (long long)dst * HIDc;
#pragma unroll
    for (int i = 0; i < 8; i++) {
        float w = __shfl_sync(0xffffffffu, ex, i >> 1);
        int c = i * 32 + lane;
        atomicAdd(&go[c], w * xl[c]);
    }
}

// ---------------- finalize: normalize, bias, residual, LN ----------------
__global__ void finalize_kernel(const float* __restrict__ gout, const float* __restrict__ denom,
                                const float* __restrict__ gbias,
                                const float* __restrict__ lng, const float* __restrict__ lnb,
                                float* __restrict__ X) {
    __shared__ float smem[16];
    int n = blockIdx.x, c = threadIdx.x;
    float v = gout[(long long)n * HIDc + c] / denom[n * HEADSc + (c >> 6)]
              + gbias[c] + X[(long long)n * HIDc + c];
    float mu, var;
    block_mean_var_256(v, smem, mu, var);
    X[(long long)n * HIDc + c] = (v - mu) * rsqrtf(var + EPSV) * lng[c] + lnb[c];
}

// ---------------- head: GELU(T) @ h2_W + h2_b, warp per node ----------------
__global__ void head2_kernel(const float* __restrict__ T, const float* __restrict__ W2,
                             const float* __restrict__ b2, float* __restrict__ out) {
    int n = blockIdx.x * 8 + (threadIdx.x >> 5);
    if (n >= Nn) return;
    int lane = threadIdx.x & 31;
    const float* t = T + (long long)n * HIDc;
    float a0 = 0.f, a1 = 0.f, a2 = 0.f;
#pragma unroll
    for (int j = 0; j < 8; j++) {
        int k = j * 32 + lane;
        float x = t[k];
        float ge = 0.5f * x * (1.f + erff(x * 0.70710678118654752440f));
        a0 += ge * W2[k * 3 + 0];
        a1 += ge * W2[k * 3 + 1];
        a2 += ge * W2[k * 3 + 2];
    }
#pragma unroll
    for (int o = 16; o > 0; o >>= 1) {
        a0 += __shfl_xor_sync(0xffffffffu, a0, o);
        a1 += __shfl_xor_sync(0xffffffffu, a1, o);
        a2 += __shfl_xor_sync(0xffffffffu, a2, o);
    }
    if (lane == 0) {
        out[n * 3 + 0] = a0 + b2[0];
        out[n * 3 + 1] = a1 + b2[1];
        out[n * 3 + 2] = a2 + b2[2];
    }
}

// ---------------- launcher ----------------
extern "C" void kernel_launch(void* const* d_in, const int* in_sizes, int n_in,
                              void* d_out, int out_size) {
    const float* features = (const float*)d_in[0];
    const void* ei = d_in[1];
    const float* proj_W = (const float*)d_in[2];
    const float* proj_b = (const float*)d_in[3];
    const float* n0_g = (const float*)d_in[4];
    const float* n0_b = (const float*)d_in[5];
    const float* Wl = (const float*)d_in[6];
    const float* bl = (const float*)d_in[7];
    const float* Wr = (const float*)d_in[8];
    const float* br = (const float*)d_in[9];
    const float* att = (const float*)d_in[10];
    const float* gbias = (const float*)d_in[11];
    const float* ln_g = (const float*)d_in[12];
    const float* ln_b = (const float*)d_in[13];
    const float* h1_W = (const float*)d_in[14];
    const float* h1_b = (const float*)d_in[15];
    const float* h2_W = (const float*)d_in[16];
    const float* h2_b = (const float*)d_in[17];
    float* out = (float*)d_out;

    int E = in_sizes[1] / 2;
    int etot = E + Nn;

    float *pX, *pTmp, *pXL, *pXR, *pLog, *pM, *pD, *pG;
    cudaGetSymbolAddress((void**)&pX, g_X);
    cudaGetSymbolAddress((void**)&pTmp, g_tmp);
    cudaGetSymbolAddress((void**)&pXL, g_XL);
    cudaGetSymbolAddress((void**)&pXR, g_XR);
    cudaGetSymbolAddress((void**)&pLog, g_logits);
    cudaGetSymbolAddress((void**)&pM, g_m);
    cudaGetSymbolAddress((void**)&pD, g_denom);
    cudaGetSymbolAddress((void**)&pG, g_gout);

    dim3 g1((Nn + 127) / 128, HIDc / 128, 1);   // single GEMM
    dim3 g2((Nn + 127) / 128, HIDc / 128, 2);   // fused Wl/Wr pair
    int edgeBlocks = (etot + 7) / 8;

    detect_idx_kernel<<<1, 32>>>(ei);

    // proj + input LN
    gemm128_kernel<<<g1, 256>>>(features, proj_W, proj_W, proj_b, proj_b,
                                pTmp, pTmp, Nn, IN_DIMc, HIDc);
    ln_kernel<<<Nn, 256>>>(pTmp, n0_g, n0_b, pX);

    for (int h = 0; h < HOPSc; h++) {
        const float* Wlh = Wl + (long long)h * HIDc * HIDc;
        const float* Wrh = Wr + (long long)h * HIDc * HIDc;
        gemm128_kernel<<<g2, 256>>>(pX, Wlh, Wrh, bl + h * HIDc, br + h * HIDc,
                                    pXL, pXR, Nn, HIDc, HIDc);
        init_seg_kernel<<<(Nn * HIDc + 255) / 256, 256>>>();
        edge_logits_kernel<<<edgeBlocks, 256>>>(ei, pXL, pXR, att + h * HEADSc * HDc,
                                                pLog, pM, E, etot);
        edge_scatter_kernel<<<edgeBlocks, 256>>>(ei, pXL, pLog, pM, pD, pG, E, etot);
        finalize_kernel<<<Nn, 256>>>(pG, pD, gbias + h * HIDc,
                                     ln_g + h * HIDc, ln_b + h * HIDc, pX);
    }

    // head
    gemm128_kernel<<<g1, 256>>>(pX, h1_W, h1_W, h1_b, h1_b, pTmp, pTmp, Nn, HIDc, HIDc);
    head2_kernel<<<(Nn + 7) / 8, 256>>>(pTmp, h2_W, h2_b, out);
}

// round 8
// speedup vs baseline: 2.6005x; 2.6005x over previous
#include <cuda_runtime.h>
#include <math.h>
#include <stdint.h>

#define Nn 20000
#define IN_DIMc 1536
#define HIDc 256
#define HEADSc 4
#define HDc 64
#define HOPSc 3
#define NCLSc 3
#define EMAXc 400000
#define EPSV 1e-5f
#define NEG_SLOPE 0.2f

// ---------------- scratch (device globals; no allocations) ----------------
__device__ float g_X[Nn * HIDc];
__device__ float g_tmp[Nn * HIDc];
__device__ float g_XL[Nn * HIDc];
__device__ float g_XR[Nn * HIDc];
__device__ float g_logits[(EMAXc + Nn) * HEADSc];
__device__ float g_m[Nn * HEADSc];
__device__ float g_denom[Nn * HEADSc];
__device__ float g_gout[Nn * HIDc];
__device__ int g_flag;  // 1 = edge_index is int64, 0 = int32

// ---------------- utilities ----------------
__device__ __forceinline__ void atomicMaxF(float* addr, float v) {
    int old = __float_as_int(*addr);
    while (v > __int_as_float(old)) {
        int assumed = old;
        old = atomicCAS((int*)addr, assumed, __float_as_int(v));
        if (old == assumed) break;
    }
}

__global__ void detect_idx_kernel(const void* __restrict__ ei) {
    if (threadIdx.x == 0 && blockIdx.x == 0) {
        const long long* p = (const long long*)ei;
        int ok = 1;
        for (int i = 0; i < 256; i++) {
            long long v = p[i];
            if (v < 0 || v >= (long long)Nn) { ok = 0; break; }
        }
        g_flag = ok;
    }
}

__device__ __forceinline__ int edge_get(const void* ei, long long idx, int flag) {
    return flag ? (int)((const long long*)ei)[idx] : ((const int*)ei)[idx];
}

// ---------------- TF32 tensor-core GEMM ----------------
// C[M,Nc] = A[M,K] @ B[K,Nc] + bias.  BM=128, BN=128, BK=16, 256 threads.
// 8 warps in 4x2; warp tile 32x64 = 2x8 mma.m16n8k8 tiles. cp.async double
// buffer. gridDim.z selects (B0,bias0,C0)/(B1,bias1,C1) to fuse GEMM pairs.
// Requires K % 16 == 0, Nc % 128 == 0.

__device__ __forceinline__ uint32_t cvt_tf32(uint32_t bits) {
    float f = __uint_as_float(bits);
    uint32_t r;
    asm("cvt.rna.tf32.f32 %0, %1;" : "=r"(r) : "f"(f));
    return r;
}

__device__ __forceinline__ void mma_tf32(float* c, uint32_t a0, uint32_t a1,
                                         uint32_t a2, uint32_t a3,
                                         uint32_t b0, uint32_t b1) {
    asm volatile(
        "mma.sync.aligned.m16n8k8.row.col.f32.tf32.tf32.f32 "
        "{%0,%1,%2,%3}, {%4,%5,%6,%7}, {%8,%9}, {%0,%1,%2,%3};"
        : "+f"(c[0]), "+f"(c[1]), "+f"(c[2]), "+f"(c[3])
        : "r"(a0), "r"(a1), "r"(a2), "r"(a3), "r"(b0), "r"(b1));
}

__device__ __forceinline__ void cp16(uint32_t saddr, const float* gptr) {
    asm volatile("cp.async.ca.shared.global [%0], [%1], 16;" ::"r"(saddr), "l"(gptr));
}

__global__ __launch_bounds__(256, 2)
void gemm_tc_kernel(const float* __restrict__ A,
                    const float* __restrict__ B0, const float* __restrict__ B1,
                    const float* __restrict__ bias0, const float* __restrict__ bias1,
                    float* __restrict__ C0, float* __restrict__ C1,
                    int M, int K, int Nc) {
    const float* __restrict__ B = blockIdx.z ? B1 : B0;
    const float* __restrict__ bias = blockIdx.z ? bias1 : bias0;
    float* __restrict__ C = blockIdx.z ? C1 : C0;

    // As[s][m][k] (pad k to 20 words -> row 80B, 16B-aligned; frag reads conflict-free)
    // Bs[s][k][n] (pad n to 136 words -> row 544B, 16B-aligned; frag reads conflict-free)
    __shared__ __align__(16) uint32_t As[2][128][20];
    __shared__ __align__(16) uint32_t Bs[2][16][136];

    int tid = threadIdx.x;
    int rm = blockIdx.x * 128, cn = blockIdx.y * 128;

    // A tile: 128 rows x 4 chunks(16B); thread handles chunks tid, tid+256
    int ar0 = tid >> 2, aq0 = (tid & 3) * 4;
    int ar1 = (tid + 256) >> 2, aq1 = (tid & 3) * 4;  // (tid+256)&3 == tid&3
    // clamp out-of-range rows to M-1 (values read but never stored)
    const float* ga0 = A + (size_t)min(rm + ar0, M - 1) * K + aq0;
    const float* ga1 = A + (size_t)min(rm + ar1, M - 1) * K + aq1;
    // B tile: 16 rows x 32 chunks
    int bk0 = tid >> 5, bq0 = (tid & 31) * 4;
    int bk1 = 8 + (tid >> 5), bq1 = bq0;
    const float* gb0 = B + (size_t)bk0 * Nc + cn + bq0;
    const float* gb1 = B + (size_t)bk1 * Nc + cn + bq1;

    uint32_t sA0[2], sA1[2], sB0[2], sB1[2];
#pragma unroll
    for (int s = 0; s < 2; s++) {
        sA0[s] = (uint32_t)__cvta_generic_to_shared(&As[s][ar0][aq0]);
        sA1[s] = (uint32_t)__cvta_generic_to_shared(&As[s][ar1][aq1]);
        sB0[s] = (uint32_t)__cvta_generic_to_shared(&Bs[s][bk0][bq0]);
        sB1[s] = (uint32_t)__cvta_generic_to_shared(&Bs[s][bk1][bq1]);
    }

    int warp = tid >> 5, lane = tid & 31, grp = lane >> 2, qid = lane & 3;
    int wm = (warp & 3) * 32, wn = (warp >> 2) * 64;

    float acc[2][8][4];
#pragma unroll
    for (int mt = 0; mt < 2; mt++)
#pragma unroll
        for (int nt = 0; nt < 8; nt++)
#pragma unroll
            for (int i = 0; i < 4; i++) acc[mt][nt][i] = 0.f;

    int ntile = K / 16;

    // prologue: stage 0
    cp16(sA0[0], ga0);
    cp16(sA1[0], ga1);
    cp16(sB0[0], gb0);
    cp16(sB1[0], gb1);
    asm volatile("cp.async.commit_group;");

    for (int t = 0; t < ntile; t++) {
        int s = t & 1;
        if (t + 1 < ntile) {
            int kt = (t + 1) * 16;
            cp16(sA0[s ^ 1], ga0 + kt);
            cp16(sA1[s ^ 1], ga1 + kt);
            cp16(sB0[s ^ 1], gb0 + (size_t)kt * Nc);
            cp16(sB1[s ^ 1], gb1 + (size_t)kt * Nc);
            asm volatile("cp.async.commit_group;");
            asm volatile("cp.async.wait_group 1;");
        } else {
            asm volatile("cp.async.wait_group 0;");
        }
        __syncthreads();

#pragma unroll
        for (int ks = 0; ks < 16; ks += 8) {
            uint32_t af[2][4];
#pragma unroll
            for (int mt = 0; mt < 2; mt++) {
                int m = wm + mt * 16 + grp;
                af[mt][0] = cvt_tf32(As[s][m][ks + qid]);
                af[mt][1] = cvt_tf32(As[s][m + 8][ks + qid]);
                af[mt][2] = cvt_tf32(As[s][m][ks + qid + 4]);
                af[mt][3] = cvt_tf32(As[s][m + 8][ks + qid + 4]);
            }
#pragma unroll
            for (int nt = 0; nt < 8; nt++) {
                int n = wn + nt * 8 + grp;
                uint32_t b0 = cvt_tf32(Bs[s][ks + qid][n]);
                uint32_t b1 = cvt_tf32(Bs[s][ks + qid + 4][n]);
                mma_tf32(acc[0][nt], af[0][0], af[0][1], af[0][2], af[0][3], b0, b1);
                mma_tf32(acc[1][nt], af[1][0], af[1][1], af[1][2], af[1][3], b0, b1);
            }
        }
        __syncthreads();
    }

    // epilogue
#pragma unroll
    for (int nt = 0; nt < 8; nt++) {
        int gcol = cn + wn + nt * 8 + qid * 2;
        float2 bb = *(const float2*)(bias + gcol);
#pragma unroll
        for (int mt = 0; mt < 2; mt++) {
            int r0 = rm + wm + mt * 16 + grp;
            int r1 = r0 + 8;
            if (r0 < M) {
                float2 o = make_float2(acc[mt][nt][0] + bb.x, acc[mt][nt][1] + bb.y);
                *(float2*)(C + (size_t)r0 * Nc + gcol) = o;
            }
            if (r1 < M) {
                float2 o = make_float2(acc[mt][nt][2] + bb.x, acc[mt][nt][3] + bb.y);
                *(float2*)(C + (size_t)r1 * Nc + gcol) = o;
            }
        }
    }
}

// ---------------- block stats helper ----------------
__device__ __forceinline__ void block_mean_var_256(float v, float* smem, float& mu, float& var) {
    float s = v, sq = v * v;
#pragma unroll
    for (int o = 16; o > 0; o >>= 1) {
        s += __shfl_xor_sync(0xffffffffu, s, o);
        sq += __shfl_xor_sync(0xffffffffu, sq, o);
    }
    int w = threadIdx.x >> 5, l = threadIdx.x & 31;
    if (l == 0) { smem[w] = s; smem[8 + w] = sq; }
    __syncthreads();
    if (w == 0) {
        s = (l < 8) ? smem[l] : 0.f;
        sq = (l < 8) ? smem[8 + l] : 0.f;
#pragma unroll
        for (int o = 4; o > 0; o >>= 1) {
            s += __shfl_xor_sync(0xffffffffu, s, o);
            sq += __shfl_xor_sync(0xffffffffu, sq, o);
        }
        if (l == 0) { smem[0] = s; smem[8] = sq; }
    }
    __syncthreads();
    mu = smem[0] * (1.f / HIDc);
    var = smem[8] * (1.f / HIDc) - mu * mu;
}

__global__ void ln_kernel(const float* __restrict__ in, const float* __restrict__ g,
                          const float* __restrict__ b, float* __restrict__ out) {
    __shared__ float smem[16];
    int n = blockIdx.x, c = threadIdx.x;
    float v = in[(long long)n * HIDc + c];
    float mu, var;
    block_mean_var_256(v, smem, mu, var);
    out[(long long)n * HIDc + c] = (v - mu) * rsqrtf(var + EPSV) * g[c] + b[c];
}

// ---------------- per-hop segment buffers init ----------------
__global__ void init_seg_kernel() {
    int i = blockIdx.x * blockDim.x + threadIdx.x;
    if (i < Nn * HIDc) g_gout[i] = 0.f;
    if (i < Nn * HEADSc) { g_m[i] = -1e30f; g_denom[i] = 0.f; }
}

// ---------------- edge pass 1: logits + segment max ----------------
__global__ void edge_logits_kernel(const void* __restrict__ ei,
                                   const float* __restrict__ XL, const float* __restrict__ XR,
                                   const float* __restrict__ att,
                                   float* __restrict__ logits, float* __restrict__ m,
                                   int E, int etot) {
    int e = blockIdx.x * 8 + (threadIdx.x >> 5);
    if (e >= etot) return;
    int lane = threadIdx.x & 31;
    int flag = g_flag;
    int src, dst;
    if (e < E) {
        src = edge_get(ei, e, flag);
        dst = edge_get(ei, (long long)E + e, flag);
    } else {
        src = dst = e - E;
    }
    const float4* xl4 = (const float4*)(XL + (long long)src * HIDc);
    const float4* xr4 = (const float4*)(XR + (long long)dst * HIDc);
    int head = lane >> 3;
    float s = 0.f;
#pragma unroll
    for (int q = 0; q < 2; q++) {
        float4 a = xl4[lane * 2 + q];
        float4 b = xr4[lane * 2 + q];
        int cbase = lane * 8 + q * 4;
        const float* ap = att + head * HDc + (cbase & 63);
        float v;
        v = a.x + b.x; v = v > 0.f ? v : NEG_SLOPE * v; s += v * ap[0];
        v = a.y + b.y; v = v > 0.f ? v : NEG_SLOPE * v; s += v * ap[1];
        v = a.z + b.z; v = v > 0.f ? v : NEG_SLOPE * v; s += v * ap[2];
        v = a.w + b.w; v = v > 0.f ? v : NEG_SLOPE * v; s += v * ap[3];
    }
    s += __shfl_xor_sync(0xffffffffu, s, 1);
    s += __shfl_xor_sync(0xffffffffu, s, 2);
    s += __shfl_xor_sync(0xffffffffu, s, 4);
    if ((lane & 7) == 0) {
        logits[(long long)e * HEADSc + head] = s;
        atomicMaxF(&m[dst * HEADSc + head], s);
    }
}

// ---------------- edge pass 2: exp + denom + weighted scatter ----------------
__global__ void edge_scatter_kernel(const void* __restrict__ ei,
                                    const float* __restrict__ XL,
                                    const float* __restrict__ logits, const float* __restrict__ m,
                                    float* __restrict__ denom, float* __restrict__ gout,
                                    int E, int etot) {
    int e = blockIdx.x * 8 + (threadIdx.x >> 5);
    if (e >= etot) return;
    int lane = threadIdx.x & 31;
    int flag = g_flag;
    int src, dst;
    if (e < E) {
        src = edge_get(ei, e, flag);
        dst = edge_get(ei, (long long)E + e, flag);
    } else {
        src = dst = e - E;
    }
    float ex = 0.f;
    if (lane < HEADSc) {
        float lo = logits[(long long)e * HEADSc + lane];
        ex = __expf(lo - m[dst * HEADSc + lane]);
        atomicAdd(&denom[dst * HEADSc + lane], ex);
    }
    const float* xl = XL + (long long)src * HIDc;
    float* go = gout + (long long)dst * HIDc;
#pragma unroll
    for (int i = 0; i < 8; i++) {
        float w = __shfl_sync(0xffffffffu, ex, i >> 1);
        int c = i * 32 + lane;
        atomicAdd(&go[c], w * xl[c]);
    }
}

// ---------------- finalize: normalize, bias, residual, LN ----------------
__global__ void finalize_kernel(const float* __restrict__ gout, const float* __restrict__ denom,
                                const float* __restrict__ gbias,
                                const float* __restrict__ lng, const float* __restrict__ lnb,
                                float* __restrict__ X) {
    __shared__ float smem[16];
    int n = blockIdx.x, c = threadIdx.x;
    float v = gout[(long long)n * HIDc + c] / denom[n * HEADSc + (c >> 6)]
              + gbias[c] + X[(long long)n * HIDc + c];
    float mu, var;
    block_mean_var_256(v, smem, mu, var);
    X[(long long)n * HIDc + c] = (v - mu) * rsqrtf(var + EPSV) * lng[c] + lnb[c];
}

// ---------------- head: GELU(T) @ h2_W + h2_b, warp per node ----------------
__global__ void head2_kernel(const float* __restrict__ T, const float* __restrict__ W2,
                             const float* __restrict__ b2, float* __restrict__ out) {
    int n = blockIdx.x * 8 + (threadIdx.x >> 5);
    if (n >= Nn) return;
    int lane = threadIdx.x & 31;
    const float* t = T + (long long)n * HIDc;
    float a0 = 0.f, a1 = 0.f, a2 = 0.f;
#pragma unroll
    for (int j = 0; j < 8; j++) {
        int k = j * 32 + lane;
        float x = t[k];
        float ge = 0.5f * x * (1.f + erff(x * 0.70710678118654752440f));
        a0 += ge * W2[k * 3 + 0];
        a1 += ge * W2[k * 3 + 1];
        a2 += ge * W2[k * 3 + 2];
    }
#pragma unroll
    for (int o = 16; o > 0; o >>= 1) {
        a0 += __shfl_xor_sync(0xffffffffu, a0, o);
        a1 += __shfl_xor_sync(0xffffffffu, a1, o);
        a2 += __shfl_xor_sync(0xffffffffu, a2, o);
    }
    if (lane == 0) {
        out[n * 3 + 0] = a0 + b2[0];
        out[n * 3 + 1] = a1 + b2[1];
        out[n * 3 + 2] = a2 + b2[2];
    }
}

// ---------------- launcher ----------------
extern "C" void kernel_launch(void* const* d_in, const int* in_sizes, int n_in,
                              void* d_out, int out_size) {
    const float* features = (const float*)d_in[0];
    const void* ei = d_in[1];
    const float* proj_W = (const float*)d_in[2];
    const float* proj_b = (const float*)d_in[3];
    const float* n0_g = (const float*)d_in[4];
    const float* n0_b = (const float*)d_in[5];
    const float* Wl = (const float*)d_in[6];
    const float* bl = (const float*)d_in[7];
    const float* Wr = (const float*)d_in[8];
    const float* br = (const float*)d_in[9];
    const float* att = (const float*)d_in[10];
    const float* gbias = (const float*)d_in[11];
    const float* ln_g = (const float*)d_in[12];
    const float* ln_b = (const float*)d_in[13];
    const float* h1_W = (const float*)d_in[14];
    const float* h1_b = (const float*)d_in[15];
    const float* h2_W = (const float*)d_in[16];
    const float* h2_b = (const float*)d_in[17];
    float* out = (float*)d_out;

    int E = in_sizes[1] / 2;
    int etot = E + Nn;

    float *pX, *pTmp, *pXL, *pXR, *pLog, *pM, *pD, *pG;
    cudaGetSymbolAddress((void**)&pX, g_X);
    cudaGetSymbolAddress((void**)&pTmp, g_tmp);
    cudaGetSymbolAddress((void**)&pXL, g_XL);
    cudaGetSymbolAddress((void**)&pXR, g_XR);
    cudaGetSymbolAddress((void**)&pLog, g_logits);
    cudaGetSymbolAddress((void**)&pM, g_m);
    cudaGetSymbolAddress((void**)&pD, g_denom);
    cudaGetSymbolAddress((void**)&pG, g_gout);

    dim3 g1((Nn + 127) / 128, HIDc / 128, 1);   // single GEMM
    dim3 g2((Nn + 127) / 128, HIDc / 128, 2);   // fused Wl/Wr pair
    int edgeBlocks = (etot + 7) / 8;

    detect_idx_kernel<<<1, 32>>>(ei);

    // proj + input LN
    gemm_tc_kernel<<<g1, 256>>>(features, proj_W, proj_W, proj_b, proj_b,
                                pTmp, pTmp, Nn, IN_DIMc, HIDc);
    ln_kernel<<<Nn, 256>>>(pTmp, n0_g, n0_b, pX);

    for (int h = 0; h < HOPSc; h++) {
        const float* Wlh = Wl + (long long)h * HIDc * HIDc;
        const float* Wrh = Wr + (long long)h * HIDc * HIDc;
        gemm_tc_kernel<<<g2, 256>>>(pX, Wlh, Wrh, bl + h * HIDc, br + h * HIDc,
                                    pXL, pXR, Nn, HIDc, HIDc);
        init_seg_kernel<<<(Nn * HIDc + 255) / 256, 256>>>();
        edge_logits_kernel<<<edgeBlocks, 256>>>(ei, pXL, pXR, att + h * HEADSc * HDc,
                                                pLog, pM, E, etot);
        edge_scatter_kernel<<<edgeBlocks, 256>>>(ei, pXL, pLog, pM, pD, pG, E, etot);
        finalize_kernel<<<Nn, 256>>>(pG, pD, gbias + h * HIDc,
                                     ln_g + h * HIDc, ln_b + h * HIDc, pX);
    }

    // head
    gemm_tc_kernel<<<g1, 256>>>(pX, h1_W, h1_W, h1_b, h1_b, pTmp, pTmp, Nn, HIDc, HIDc);
    head2_kernel<<<(Nn + 7) / 8, 256>>>(pTmp, h2_W, h2_b, out);
}

// round 9
// speedup vs baseline: 4.4936x; 1.7280x over previous
#include <cuda_runtime.h>
#include <math.h>
#include <stdint.h>

#define Nn 20000
#define IN_DIMc 1536
#define HIDc 256
#define HEADSc 4
#define HDc 64
#define HOPSc 3
#define NCLSc 3
#define EMAXc 400000
#define EPSV 1e-5f
#define NEG_SLOPE 0.2f

// ---------------- scratch (device globals; no allocations) ----------------
__device__ float g_X[Nn * HIDc];
__device__ float g_tmp[Nn * HIDc];
__device__ float g_XL[Nn * HIDc];
__device__ float g_XR[Nn * HIDc];
__device__ float g_gout[Nn * HIDc];
__device__ int g_deg[Nn];
__device__ int g_rowptr[Nn + 1];
__device__ int g_cursor[Nn];
__device__ int g_esrc[EMAXc];
__device__ int g_flag;  // 1 = edge_index is int64, 0 = int32

// ---------------- dtype probe ----------------
__global__ void detect_idx_kernel(const void* __restrict__ ei) {
    if (threadIdx.x == 0 && blockIdx.x == 0) {
        const long long* p = (const long long*)ei;
        int ok = 1;
        for (int i = 0; i < 256; i++) {
            long long v = p[i];
            if (v < 0 || v >= (long long)Nn) { ok = 0; break; }
        }
        g_flag = ok;
    }
}

__device__ __forceinline__ int edge_get(const void* ei, long long idx, int flag) {
    return flag ? (int)((const long long*)ei)[idx] : ((const int*)ei)[idx];
}

// ---------------- CSR build (once per launch; edges are hop-invariant) ----
__global__ void deg_zero_kernel() {
    int i = blockIdx.x * blockDim.x + threadIdx.x;
    if (i < Nn) g_deg[i] = 0;
}

__global__ void hist_kernel(const void* __restrict__ ei, int E) {
    int e = blockIdx.x * blockDim.x + threadIdx.x;
    if (e >= E) return;
    int dst = edge_get(ei, (long long)E + e, g_flag);
    atomicAdd(&g_deg[dst], 1);
}

// single-block inclusive scan -> exclusive rowptr; also primes cursor.
__global__ void scan_kernel() {
    __shared__ int sh[1024];
    __shared__ int carry;
    if (threadIdx.x == 0) { carry = 0; g_rowptr[0] = 0; }
    __syncthreads();
    for (int base = 0; base < Nn; base += 1024) {
        int i = base + threadIdx.x;
        int v = (i < Nn) ? g_deg[i] : 0;
        sh[threadIdx.x] = v;
        __syncthreads();
#pragma unroll
        for (int off = 1; off < 1024; off <<= 1) {
            int t = (threadIdx.x >= off) ? sh[threadIdx.x - off] : 0;
            __syncthreads();
            sh[threadIdx.x] += t;
            __syncthreads();
        }
        if (i < Nn) {
            int incl = carry + sh[threadIdx.x];
            g_rowptr[i + 1] = incl;
            g_cursor[i] = incl - v;  // exclusive prefix = row start
        }
        __syncthreads();
        if (threadIdx.x == 0) carry += sh[1023];
        __syncthreads();
    }
}

__global__ void fill_kernel(const void* __restrict__ ei, int E) {
    int e = blockIdx.x * blockDim.x + threadIdx.x;
    if (e >= E) return;
    int flag = g_flag;
    int src = edge_get(ei, e, flag);
    int dst = edge_get(ei, (long long)E + e, flag);
    int pos = atomicAdd(&g_cursor[dst], 1);
    g_esrc[pos] = src;
}

// ---------------- TF32 tensor-core GEMM ----------------
__device__ __forceinline__ uint32_t cvt_tf32(uint32_t bits) {
    float f = __uint_as_float(bits);
    uint32_t r;
    asm("cvt.rna.tf32.f32 %0, %1;" : "=r"(r) : "f"(f));
    return r;
}

__device__ __forceinline__ void mma_tf32(float* c, uint32_t a0, uint32_t a1,
                                         uint32_t a2, uint32_t a3,
                                         uint32_t b0, uint32_t b1) {
    asm volatile(
        "mma.sync.aligned.m16n8k8.row.col.f32.tf32.tf32.f32 "
        "{%0,%1,%2,%3}, {%4,%5,%6,%7}, {%8,%9}, {%0,%1,%2,%3};"
        : "+f"(c[0]), "+f"(c[1]), "+f"(c[2]), "+f"(c[3])
        : "r"(a0), "r"(a1), "r"(a2), "r"(a3), "r"(b0), "r"(b1));
}

__device__ __forceinline__ void cp16(uint32_t saddr, const float* gptr) {
    asm volatile("cp.async.ca.shared.global [%0], [%1], 16;" ::"r"(saddr), "l"(gptr));
}

__global__ __launch_bounds__(256, 2)
void gemm_tc_kernel(const float* __restrict__ A,
                    const float* __restrict__ B0, const float* __restrict__ B1,
                    const float* __restrict__ bias0, const float* __restrict__ bias1,
                    float* __restrict__ C0, float* __restrict__ C1,
                    int M, int K, int Nc) {
    const float* __restrict__ B = blockIdx.z ? B1 : B0;
    const float* __restrict__ bias = blockIdx.z ? bias1 : bias0;
    float* __restrict__ C = blockIdx.z ? C1 : C0;

    __shared__ __align__(16) uint32_t As[2][128][20];
    __shared__ __align__(16) uint32_t Bs[2][16][136];

    int tid = threadIdx.x;
    int rm = blockIdx.x * 128, cn = blockIdx.y * 128;

    int ar0 = tid >> 2, aq0 = (tid & 3) * 4;
    int ar1 = (tid + 256) >> 2, aq1 = aq0;
    const float* ga0 = A + (size_t)min(rm + ar0, M - 1) * K + aq0;
    const float* ga1 = A + (size_t)min(rm + ar1, M - 1) * K + aq1;
    int bk0 = tid >> 5, bq0 = (tid & 31) * 4;
    int bk1 = 8 + (tid >> 5);
    const float* gb0 = B + (size_t)bk0 * Nc + cn + bq0;
    const float* gb1 = B + (size_t)bk1 * Nc + cn + bq0;

    uint32_t sA0[2], sA1[2], sB0[2], sB1[2];
#pragma unroll
    for (int s = 0; s < 2; s++) {
        sA0[s] = (uint32_t)__cvta_generic_to_shared(&As[s][ar0][aq0]);
        sA1[s] = (uint32_t)__cvta_generic_to_shared(&As[s][ar1][aq1]);
        sB0[s] = (uint32_t)__cvta_generic_to_shared(&Bs[s][bk0][bq0]);
        sB1[s] = (uint32_t)__cvta_generic_to_shared(&Bs[s][bk1][bq0]);
    }

    int warp = tid >> 5, lane = tid & 31, grp = lane >> 2, qid = lane & 3;
    int wm = (warp & 3) * 32, wn = (warp >> 2) * 64;

    float acc[2][8][4];
#pragma unroll
    for (int mt = 0; mt < 2; mt++)
#pragma unroll
        for (int nt = 0; nt < 8; nt++)
#pragma unroll
            for (int i = 0; i < 4; i++) acc[mt][nt][i] = 0.f;

    int ntile = K / 16;

    cp16(sA0[0], ga0);
    cp16(sA1[0], ga1);
    cp16(sB0[0], gb0);
    cp16(sB1[0], gb1);
    asm volatile("cp.async.commit_group;");

    for (int t = 0; t < ntile; t++) {
        int s = t & 1;
        if (t + 1 < ntile) {
            int kt = (t + 1) * 16;
            cp16(sA0[s ^ 1], ga0 + kt);
            cp16(sA1[s ^ 1], ga1 + kt);
            cp16(sB0[s ^ 1], gb0 + (size_t)kt * Nc);
            cp16(sB1[s ^ 1], gb1 + (size_t)kt * Nc);
            asm volatile("cp.async.commit_group;");
            asm volatile("cp.async.wait_group 1;");
        } else {
            asm volatile("cp.async.wait_group 0;");
        }
        __syncthreads();

#pragma unroll
        for (int ks = 0; ks < 16; ks += 8) {
            uint32_t af[2][4];
#pragma unroll
            for (int mt = 0; mt < 2; mt++) {
                int m = wm + mt * 16 + grp;
                af[mt][0] = cvt_tf32(As[s][m][ks + qid]);
                af[mt][1] = cvt_tf32(As[s][m + 8][ks + qid]);
                af[mt][2] = cvt_tf32(As[s][m][ks + qid + 4]);
                af[mt][3] = cvt_tf32(As[s][m + 8][ks + qid + 4]);
            }
#pragma unroll
            for (int nt = 0; nt < 8; nt++) {
                int n = wn + nt * 8 + grp;
                uint32_t b0 = cvt_tf32(Bs[s][ks + qid][n]);
                uint32_t b1 = cvt_tf32(Bs[s][ks + qid + 4][n]);
                mma_tf32(acc[0][nt], af[0][0], af[0][1], af[0][2], af[0][3], b0, b1);
                mma_tf32(acc[1][nt], af[1][0], af[1][1], af[1][2], af[1][3], b0, b1);
            }
        }
        __syncthreads();
    }

#pragma unroll
    for (int nt = 0; nt < 8; nt++) {
        int gcol = cn + wn + nt * 8 + qid * 2;
        float2 bb = *(const float2*)(bias + gcol);
#pragma unroll
        for (int mt = 0; mt < 2; mt++) {
            int r0 = rm + wm + mt * 16 + grp;
            int r1 = r0 + 8;
            if (r0 < M) {
                float2 o = make_float2(acc[mt][nt][0] + bb.x, acc[mt][nt][1] + bb.y);
                *(float2*)(C + (size_t)r0 * Nc + gcol) = o;
            }
            if (r1 < M) {
                float2 o = make_float2(acc[mt][nt][2] + bb.x, acc[mt][nt][3] + bb.y);
                *(float2*)(C + (size_t)r1 * Nc + gcol) = o;
            }
        }
    }
}

// ---------------- fused edge aggregation: warp per dst, online softmax ----
// lane owns columns c = lane*8 + j (j=0..7); head = c>>6 = lane>>3 is uniform
// across a lane's 8 columns, so per-head softmax state (m, d) is per-lane.
// att flat index == c (HEADS*HD layout matches column layout exactly).
__global__ __launch_bounds__(256)
void edge_agg_kernel(const float* __restrict__ XL, const float* __restrict__ XR,
                     const float* __restrict__ att, float* __restrict__ gout) {
    int n = blockIdx.x * 8 + (threadIdx.x >> 5);
    if (n >= Nn) return;
    int lane = threadIdx.x & 31;

    // per-lane column block
    const float4* xr4 = (const float4*)(XR + (size_t)n * HIDc) + lane * 2;
    const float4* at4 = (const float4*)att + lane * 2;
    float4 xr0 = xr4[0], xr1 = xr4[1];
    float4 at0 = at4[0], at1 = at4[1];

    float m = -1e30f, d = 0.f;
    float acc[8];
#pragma unroll
    for (int j = 0; j < 8; j++) acc[j] = 0.f;

    int beg = g_rowptr[n], end = g_rowptr[n + 1];
    // iterate real in-edges then the self loop
    for (int e = beg; e <= end; e++) {
        int src = (e < end) ? __ldg(&g_esrc[e]) : n;
        const float4* xl4 = (const float4*)(XL + (size_t)src * HIDc) + lane * 2;
        float4 a0 = xl4[0], a1 = xl4[1];

        // partial logit for this lane's 8 columns
        float s, v;
        v = a0.x + xr0.x; v = v > 0.f ? v : NEG_SLOPE * v; s  = v * at0.x;
        v = a0.y + xr0.y; v = v > 0.f ? v : NEG_SLOPE * v; s += v * at0.y;
        v = a0.z + xr0.z; v = v > 0.f ? v : NEG_SLOPE * v; s += v * at0.z;
        v = a0.w + xr0.w; v = v > 0.f ? v : NEG_SLOPE * v; s += v * at0.w;
        v = a1.x + xr1.x; v = v > 0.f ? v : NEG_SLOPE * v; s += v * at1.x;
        v = a1.y + xr1.y; v = v > 0.f ? v : NEG_SLOPE * v; s += v * at1.y;
        v = a1.z + xr1.z; v = v > 0.f ? v : NEG_SLOPE * v; s += v * at1.z;
        v = a1.w + xr1.w; v = v > 0.f ? v : NEG_SLOPE * v; s += v * at1.w;
        // reduce within the 8-lane head group -> logit for head lane>>3
        s += __shfl_xor_sync(0xffffffffu, s, 1);
        s += __shfl_xor_sync(0xffffffffu, s, 2);
        s += __shfl_xor_sync(0xffffffffu, s, 4);

        // online softmax update
        float nm = fmaxf(m, s);
        float sc = __expf(m - nm);
        float w = __expf(s - nm);
        d = d * sc + w;
        acc[0] = acc[0] * sc + w * a0.x;
        acc[1] = acc[1] * sc + w * a0.y;
        acc[2] = acc[2] * sc + w * a0.z;
        acc[3] = acc[3] * sc + w * a0.w;
        acc[4] = acc[4] * sc + w * a1.x;
        acc[5] = acc[5] * sc + w * a1.y;
        acc[6] = acc[6] * sc + w * a1.z;
        acc[7] = acc[7] * sc + w * a1.w;
        m = nm;
    }

    float inv = 1.f / d;
    float4* go = (float4*)(gout + (size_t)n * HIDc) + lane * 2;
    go[0] = make_float4(acc[0] * inv, acc[1] * inv, acc[2] * inv, acc[3] * inv);
    go[1] = make_float4(acc[4] * inv, acc[5] * inv, acc[6] * inv, acc[7] * inv);
}

// ---------------- block stats helper ----------------
__device__ __forceinline__ void block_mean_var_256(float v, float* smem, float& mu, float& var) {
    float s = v, sq = v * v;
#pragma unroll
    for (int o = 16; o > 0; o >>= 1) {
        s += __shfl_xor_sync(0xffffffffu, s, o);
        sq += __shfl_xor_sync(0xffffffffu, sq, o);
    }
    int w = threadIdx.x >> 5, l = threadIdx.x & 31;
    if (l == 0) { smem[w] = s; smem[8 + w] = sq; }
    __syncthreads();
    if (w == 0) {
        s = (l < 8) ? smem[l] : 0.f;
        sq = (l < 8) ? smem[8 + l] : 0.f;
#pragma unroll
        for (int o = 4; o > 0; o >>= 1) {
            s += __shfl_xor_sync(0xffffffffu, s, o);
            sq += __shfl_xor_sync(0xffffffffu, sq, o);
        }
        if (l == 0) { smem[0] = s; smem[8] = sq; }
    }
    __syncthreads();
    mu = smem[0] * (1.f / HIDc);
    var = smem[8] * (1.f / HIDc) - mu * mu;
}

__global__ void ln_kernel(const float* __restrict__ in, const float* __restrict__ g,
                          const float* __restrict__ b, float* __restrict__ out) {
    __shared__ float smem[16];
    int n = blockIdx.x, c = threadIdx.x;
    float v = in[(size_t)n * HIDc + c];
    float mu, var;
    block_mean_var_256(v, smem, mu, var);
    out[(size_t)n * HIDc + c] = (v - mu) * rsqrtf(var + EPSV) * g[c] + b[c];
}

// ---------------- finalize: bias, residual, LN (no division needed) ------
__global__ void finalize_kernel(const float* __restrict__ gout,
                                const float* __restrict__ gbias,
                                const float* __restrict__ lng, const float* __restrict__ lnb,
                                float* __restrict__ X) {
    __shared__ float smem[16];
    int n = blockIdx.x, c = threadIdx.x;
    float v = gout[(size_t)n * HIDc + c] + gbias[c] + X[(size_t)n * HIDc + c];
    float mu, var;
    block_mean_var_256(v, smem, mu, var);
    X[(size_t)n * HIDc + c] = (v - mu) * rsqrtf(var + EPSV) * lng[c] + lnb[c];
}

// ---------------- head: GELU(T) @ h2_W + h2_b, warp per node ----------------
__global__ void head2_kernel(const float* __restrict__ T, const float* __restrict__ W2,
                             const float* __restrict__ b2, float* __restrict__ out) {
    int n = blockIdx.x * 8 + (threadIdx.x >> 5);
    if (n >= Nn) return;
    int lane = threadIdx.x & 31;
    const float* t = T + (size_t)n * HIDc;
    float a0 = 0.f, a1 = 0.f, a2 = 0.f;
#pragma unroll
    for (int j = 0; j < 8; j++) {
        int k = j * 32 + lane;
        float x = t[k];
        float ge = 0.5f * x * (1.f + erff(x * 0.70710678118654752440f));
        a0 += ge * W2[k * 3 + 0];
        a1 += ge * W2[k * 3 + 1];
        a2 += ge * W2[k * 3 + 2];
    }
#pragma unroll
    for (int o = 16; o > 0; o >>= 1) {
        a0 += __shfl_xor_sync(0xffffffffu, a0, o);
        a1 += __shfl_xor_sync(0xffffffffu, a1, o);
        a2 += __shfl_xor_sync(0xffffffffu, a2, o);
    }
    if (lane == 0) {
        out[n * 3 + 0] = a0 + b2[0];
        out[n * 3 + 1] = a1 + b2[1];
        out[n * 3 + 2] = a2 + b2[2];
    }
}

// ---------------- launcher ----------------
extern "C" void kernel_launch(void* const* d_in, const int* in_sizes, int n_in,
                              void* d_out, int out_size) {
    const float* features = (const float*)d_in[0];
    const void* ei = d_in[1];
    const float* proj_W = (const float*)d_in[2];
    const float* proj_b = (const float*)d_in[3];
    const float* n0_g = (const float*)d_in[4];
    const float* n0_b = (const float*)d_in[5];
    const float* Wl = (const float*)d_in[6];
    const float* bl = (const float*)d_in[7];
    const float* Wr = (const float*)d_in[8];
    const float* br = (const float*)d_in[9];
    const float* att = (const float*)d_in[10];
    const float* gbias = (const float*)d_in[11];
    const float* ln_g = (const float*)d_in[12];
    const float* ln_b = (const float*)d_in[13];
    const float* h1_W = (const float*)d_in[14];
    const float* h1_b = (const float*)d_in[15];
    const float* h2_W = (const float*)d_in[16];
    const float* h2_b = (const float*)d_in[17];
    float* out = (float*)d_out;

    int E = in_sizes[1] / 2;

    float *pX, *pTmp, *pXL, *pXR, *pG;
    cudaGetSymbolAddress((void**)&pX, g_X);
    cudaGetSymbolAddress((void**)&pTmp, g_tmp);
    cudaGetSymbolAddress((void**)&pXL, g_XL);
    cudaGetSymbolAddress((void**)&pXR, g_XR);
    cudaGetSymbolAddress((void**)&pG, g_gout);

    dim3 g1((Nn + 127) / 128, HIDc / 128, 1);
    dim3 g2((Nn + 127) / 128, HIDc / 128, 2);
    int nodeWarpBlocks = (Nn + 7) / 8;

    detect_idx_kernel<<<1, 32>>>(ei);

    // CSR build (overlaps conceptually with proj GEMM on the same stream order)
    deg_zero_kernel<<<(Nn + 255) / 256, 256>>>();
    hist_kernel<<<(E + 255) / 256, 256>>>(ei, E);
    scan_kernel<<<1, 1024>>>();
    fill_kernel<<<(E + 255) / 256, 256>>>(ei, E);

    // proj + input LN
    gemm_tc_kernel<<<g1, 256>>>(features, proj_W, proj_W, proj_b, proj_b,
                                pTmp, pTmp, Nn, IN_DIMc, HIDc);
    ln_kernel<<<Nn, 256>>>(pTmp, n0_g, n0_b, pX);

    for (int h = 0; h < HOPSc; h++) {
        const float* Wlh = Wl + (size_t)h * HIDc * HIDc;
        const float* Wrh = Wr + (size_t)h * HIDc * HIDc;
        gemm_tc_kernel<<<g2, 256>>>(pX, Wlh, Wrh, bl + h * HIDc, br + h * HIDc,
                                    pXL, pXR, Nn, HIDc, HIDc);
        edge_agg_kernel<<<nodeWarpBlocks, 256>>>(pXL, pXR, att + h * HEADSc * HDc, pG);
        finalize_kernel<<<Nn, 256>>>(pG, gbias + h * HIDc,
                                     ln_g + h * HIDc, ln_b + h * HIDc, pX);
    }

    // head
    gemm_tc_kernel<<<g1, 256>>>(pX, h1_W, h1_W, h1_b, h1_b, pTmp, pTmp, Nn, HIDc, HIDc);
    head2_kernel<<<(Nn + 7) / 8, 256>>>(pTmp, h2_W, h2_b, out);
}

// round 12
// speedup vs baseline: 4.9110x; 1.0929x over previous
#include <cuda_runtime.h>
#include <math.h>
#include <stdint.h>

#define Nn 20000
#define IN_DIMc 1536
#define HIDc 256
#define HEADSc 4
#define HDc 64
#define HOPSc 3
#define NCLSc 3
#define EMAXc 400000
#define EPSV 1e-5f
#define NEG_SLOPE 0.2f

// ---------------- scratch (device globals; no allocations) ----------------
__device__ float g_X[Nn * HIDc];
__device__ float g_tmp[Nn * HIDc];
__device__ float g_XL[Nn * HIDc];
__device__ float g_XR[Nn * HIDc];
__device__ int g_deg[Nn];
__device__ int g_rowptr[Nn + 1];
__device__ int g_cursor[Nn];
__device__ int g_esrc[EMAXc];
__device__ int g_flag;  // 1 = edge_index is int64, 0 = int32

// ---------------- dtype probe ----------------
__global__ void detect_idx_kernel(const void* __restrict__ ei) {
    if (threadIdx.x == 0 && blockIdx.x == 0) {
        const long long* p = (const long long*)ei;
        int ok = 1;
        for (int i = 0; i < 256; i++) {
            long long v = p[i];
            if (v < 0 || v >= (long long)Nn) { ok = 0; break; }
        }
        g_flag = ok;
    }
}

__device__ __forceinline__ int edge_get(const void* ei, long long idx, int flag) {
    return flag ? (int)((const long long*)ei)[idx] : ((const int*)ei)[idx];
}

// ---------------- CSR build (once per launch; edges are hop-invariant) ----
__global__ void deg_zero_kernel() {
    int i = blockIdx.x * blockDim.x + threadIdx.x;
    if (i < Nn) g_deg[i] = 0;
}

__global__ void hist_kernel(const void* __restrict__ ei, int E) {
    int e = blockIdx.x * blockDim.x + threadIdx.x;
    if (e >= E) return;
    int dst = edge_get(ei, (long long)E + e, g_flag);
    atomicAdd(&g_deg[dst], 1);
}

// single block, 1024 threads, 20 elems/thread sequential + warp/block scan.
__global__ void scan_kernel() {
    const int PER = 20;  // 1024*20 = 20480 >= Nn
    __shared__ int wsum[32];
    __shared__ int wexcl[32];
    int tid = threadIdx.x, lane = tid & 31, wid = tid >> 5;
    int base = tid * PER;

    int deg[PER];
    int tot = 0;
#pragma unroll
    for (int i = 0; i < PER; i++) {
        int idx = base + i;
        deg[i] = (idx < Nn) ? g_deg[idx] : 0;
        tot += deg[i];
    }
    // warp inclusive scan of per-thread totals
    int incl = tot;
#pragma unroll
    for (int o = 1; o < 32; o <<= 1) {
        int t = __shfl_up_sync(0xffffffffu, incl, o);
        if (lane >= o) incl += t;
    }
    if (lane == 31) wsum[wid] = incl;
    __syncthreads();
    if (wid == 0) {
        int v = wsum[lane];
        int s = v;
#pragma unroll
        for (int o = 1; o < 32; o <<= 1) {
            int t = __shfl_up_sync(0xffffffffu, s, o);
            if (lane >= o) s += t;
        }
        wexcl[lane] = s - v;
    }
    __syncthreads();

    int running = wexcl[wid] + (incl - tot);  // exclusive prefix for this thread
#pragma unroll
    for (int i = 0; i < PER; i++) {
        int idx = base + i;
        if (idx < Nn) {
            g_cursor[idx] = running;
            running += deg[i];
            g_rowptr[idx + 1] = running;
        }
    }
    if (tid == 0) g_rowptr[0] = 0;
}

__global__ void fill_kernel(const void* __restrict__ ei, int E) {
    int e = blockIdx.x * blockDim.x + threadIdx.x;
    if (e >= E) return;
    int flag = g_flag;
    int src = edge_get(ei, e, flag);
    int dst = edge_get(ei, (long long)E + e, flag);
    int pos = atomicAdd(&g_cursor[dst], 1);
    g_esrc[pos] = src;
}

// ---------------- TF32 tensor-core GEMM (3-stage cp.async pipeline) ------
__device__ __forceinline__ uint32_t cvt_tf32(uint32_t bits) {
    float f = __uint_as_float(bits);
    uint32_t r;
    asm("cvt.rna.tf32.f32 %0, %1;" : "=r"(r) : "f"(f));
    return r;
}

__device__ __forceinline__ void mma_tf32(float* c, uint32_t a0, uint32_t a1,
                                         uint32_t a2, uint32_t a3,
                                         uint32_t b0, uint32_t b1) {
    asm volatile(
        "mma.sync.aligned.m16n8k8.row.col.f32.tf32.tf32.f32 "
        "{%0,%1,%2,%3}, {%4,%5,%6,%7}, {%8,%9}, {%0,%1,%2,%3};"
        : "+f"(c[0]), "+f"(c[1]), "+f"(c[2]), "+f"(c[3])
        : "r"(a0), "r"(a1), "r"(a2), "r"(a3), "r"(b0), "r"(b1));
}

__device__ __forceinline__ void cp16(uint32_t saddr, const float* gptr) {
    asm volatile("cp.async.ca.shared.global [%0], [%1], 16;" ::"r"(saddr), "l"(gptr));
}

#define ASTRIDE 20
#define BSTRIDE 136
#define AWORDS (128 * ASTRIDE)
#define BWORDS (16 * BSTRIDE)
#define GEMM_SMEM (3 * (AWORDS + BWORDS) * 4)

__global__ __launch_bounds__(256, 2)
void gemm_tc_kernel(const float* __restrict__ A,
                    const float* __restrict__ B0, const float* __restrict__ B1,
                    const float* __restrict__ bias0, const float* __restrict__ bias1,
                    float* __restrict__ C0, float* __restrict__ C1,
                    int M, int K, int Nc) {
    const float* __restrict__ B = blockIdx.z ? B1 : B0;
    const float* __restrict__ bias = blockIdx.z ? bias1 : bias0;
    float* __restrict__ C = blockIdx.z ? C1 : C0;

    extern __shared__ __align__(16) uint32_t dyn[];
    uint32_t* Asm = dyn;                 // [3][128][ASTRIDE]
    uint32_t* Bsm = dyn + 3 * AWORDS;    // [3][16][BSTRIDE]

    int tid = threadIdx.x;
    int rm = blockIdx.x * 128, cn = blockIdx.y * 128;

    int ar0 = tid >> 2, aq = (tid & 3) * 4;
    int ar1 = ar0 + 64;
    const float* ga0 = A + (size_t)min(rm + ar0, M - 1) * K + aq;
    const float* ga1 = A + (size_t)min(rm + ar1, M - 1) * K + aq;
    int bk0 = tid >> 5, bq = (tid & 31) * 4;
    int bk1 = bk0 + 8;
    const float* gb0 = B + (size_t)bk0 * Nc + cn + bq;
    const float* gb1 = B + (size_t)bk1 * Nc + cn + bq;

    uint32_t sA0[3], sA1[3], sB0[3], sB1[3];
#pragma unroll
    for (int s = 0; s < 3; s++) {
        sA0[s] = (uint32_t)__cvta_generic_to_shared(Asm + s * AWORDS + ar0 * ASTRIDE + aq);
        sA1[s] = (uint32_t)__cvta_generic_to_shared(Asm + s * AWORDS + ar1 * ASTRIDE + aq);
        sB0[s] = (uint32_t)__cvta_generic_to_shared(Bsm + s * BWORDS + bk0 * BSTRIDE + bq);
        sB1[s] = (uint32_t)__cvta_generic_to_shared(Bsm + s * BWORDS + bk1 * BSTRIDE + bq);
    }

    int warp = tid >> 5, lane = tid & 31, grp = lane >> 2, qid = lane & 3;
    int wm = (warp & 3) * 32, wn = (warp >> 2) * 64;

    float acc[2][8][4];
#pragma unroll
    for (int mt = 0; mt < 2; mt++)
#pragma unroll
        for (int nt = 0; nt < 8; nt++)
#pragma unroll
            for (int i = 0; i < 4; i++) acc[mt][nt][i] = 0.f;

    int ntile = K / 16;

    // prologue: stages 0,1
#pragma unroll
    for (int p = 0; p < 2; p++) {
        if (p < ntile) {
            int kt = p * 16;
            cp16(sA0[p], ga0 + kt);
            cp16(sA1[p], ga1 + kt);
            cp16(sB0[p], gb0 + (size_t)kt * Nc);
            cp16(sB1[p], gb1 + (size_t)kt * Nc);
        }
        asm volatile("cp.async.commit_group;");
    }

    int stage = 0;
    for (int t = 0; t < ntile; t++) {
        if (t + 2 < ntile) {
            int kt = (t + 2) * 16;
            int ps = (stage + 2) % 3;
            cp16(sA0[ps], ga0 + kt);
            cp16(sA1[ps], ga1 + kt);
            cp16(sB0[ps], gb0 + (size_t)kt * Nc);
            cp16(sB1[ps], gb1 + (size_t)kt * Nc);
            asm volatile("cp.async.commit_group;");
            asm volatile("cp.async.wait_group 2;");
        } else if (t + 1 < ntile) {
            asm volatile("cp.async.wait_group 1;");
        } else {
            asm volatile("cp.async.wait_group 0;");
        }
        __syncthreads();

        const uint32_t* As = Asm + stage * AWORDS;
        const uint32_t* Bs = Bsm + stage * BWORDS;
#pragma unroll
        for (int ks = 0; ks < 16; ks += 8) {
            uint32_t af[2][4];
#pragma unroll
            for (int mt = 0; mt < 2; mt++) {
                int m = wm + mt * 16 + grp;
                af[mt][0] = cvt_tf32(As[m * ASTRIDE + ks + qid]);
                af[mt][1] = cvt_tf32(As[(m + 8) * ASTRIDE + ks + qid]);
                af[mt][2] = cvt_tf32(As[m * ASTRIDE + ks + qid + 4]);
                af[mt][3] = cvt_tf32(As[(m + 8) * ASTRIDE + ks + qid + 4]);
            }
#pragma unroll
            for (int nt = 0; nt < 8; nt++) {
                int n = wn + nt * 8 + grp;
                uint32_t b0 = cvt_tf32(Bs[(ks + qid) * BSTRIDE + n]);
                uint32_t b1 = cvt_tf32(Bs[(ks + qid + 4) * BSTRIDE + n]);
                mma_tf32(acc[0][nt], af[0][0], af[0][1], af[0][2], af[0][3], b0, b1);
                mma_tf32(acc[1][nt], af[1][0], af[1][1], af[1][2], af[1][3], b0, b1);
            }
        }
        __syncthreads();
        stage = (stage + 1) % 3;
    }

#pragma unroll
    for (int nt = 0; nt < 8; nt++) {
        int gcol = cn + wn + nt * 8 + qid * 2;
        float2 bb = *(const float2*)(bias + gcol);
#pragma unroll
        for (int mt = 0; mt < 2; mt++) {
            int r0 = rm + wm + mt * 16 + grp;
            int r1 = r0 + 8;
            if (r0 < M) {
                float2 o = make_float2(acc[mt][nt][0] + bb.x, acc[mt][nt][1] + bb.y);
                *(float2*)(C + (size_t)r0 * Nc + gcol) = o;
            }
            if (r1 < M) {
                float2 o = make_float2(acc[mt][nt][2] + bb.x, acc[mt][nt][3] + bb.y);
                *(float2*)(C + (size_t)r1 * Nc + gcol) = o;
            }
        }
    }
}

// ---------------- fused edge aggregation + bias/residual/LN --------------
// Warp per dst node. Lane owns columns c = lane*8+j; head = lane>>3 uniform
// per lane, so per-head softmax state is per-lane. After aggregation the warp
// holds the full 256-col row, so LayerNorm completes in-warp via shuffles.
__global__ __launch_bounds__(256)
void edge_agg_kernel(const float* __restrict__ XL, const float* __restrict__ XR,
                     const float* __restrict__ att,
                     const float* __restrict__ gbias,
                     const float* __restrict__ lng, const float* __restrict__ lnb,
                     float* __restrict__ X) {
    int n = blockIdx.x * 8 + (threadIdx.x >> 5);
    if (n >= Nn) return;
    int lane = threadIdx.x & 31;

    const float4* xr4 = (const float4*)(XR + (size_t)n * HIDc) + lane * 2;
    const float4* at4 = (const float4*)att + lane * 2;
    float4 xr0 = xr4[0], xr1 = xr4[1];
    float4 at0 = at4[0], at1 = at4[1];

    float m = -1e30f, d = 0.f;
    float acc[8];
#pragma unroll
    for (int j = 0; j < 8; j++) acc[j] = 0.f;

    int beg = g_rowptr[n], end = g_rowptr[n + 1];
    for (int e = beg; e <= end; e++) {
        int src = (e < end) ? __ldg(&g_esrc[e]) : n;  // self loop last
        const float4* xl4 = (const float4*)(XL + (size_t)src * HIDc) + lane * 2;
        float4 a0 = xl4[0], a1 = xl4[1];

        float s, v;
        v = a0.x + xr0.x; v = v > 0.f ? v : NEG_SLOPE * v; s  = v * at0.x;
        v = a0.y + xr0.y; v = v > 0.f ? v : NEG_SLOPE * v; s += v * at0.y;
        v = a0.z + xr0.z; v = v > 0.f ? v : NEG_SLOPE * v; s += v * at0.z;
        v = a0.w + xr0.w; v = v > 0.f ? v : NEG_SLOPE * v; s += v * at0.w;
        v = a1.x + xr1.x; v = v > 0.f ? v : NEG_SLOPE * v; s += v * at1.x;
        v = a1.y + xr1.y; v = v > 0.f ? v : NEG_SLOPE * v; s += v * at1.y;
        v = a1.z + xr1.z; v = v > 0.f ? v : NEG_SLOPE * v; s += v * at1.z;
        v = a1.w + xr1.w; v = v > 0.f ? v : NEG_SLOPE * v; s += v * at1.w;
        s += __shfl_xor_sync(0xffffffffu, s, 1);
        s += __shfl_xor_sync(0xffffffffu, s, 2);
        s += __shfl_xor_sync(0xffffffffu, s, 4);

        float nm = fmaxf(m, s);
        float sc = __expf(m - nm);
        float w = __expf(s - nm);
        d = d * sc + w;
        acc[0] = acc[0] * sc + w * a0.x;
        acc[1] = acc[1] * sc + w * a0.y;
        acc[2] = acc[2] * sc + w * a0.z;
        acc[3] = acc[3] * sc + w * a0.w;
        acc[4] = acc[4] * sc + w * a1.x;
        acc[5] = acc[5] * sc + w * a1.y;
        acc[6] = acc[6] * sc + w * a1.z;
        acc[7] = acc[7] * sc + w * a1.w;
        m = nm;
    }

    float inv = 1.f / d;
    // v = attn_out + gbias + residual
    float4* xrow = (float4*)(X + (size_t)n * HIDc) + lane * 2;
    float4 x0 = xrow[0], x1 = xrow[1];
    const float4* gb4 = (const float4*)gbias + lane * 2;
    float4 gb0 = gb4[0], gb1 = gb4[1];
    float v[8];
    v[0] = acc[0] * inv + gb0.x + x0.x;
    v[1] = acc[1] * inv + gb0.y + x0.y;
    v[2] = acc[2] * inv + gb0.z + x0.z;
    v[3] = acc[3] * inv + gb0.w + x0.w;
    v[4] = acc[4] * inv + gb1.x + x1.x;
    v[5] = acc[5] * inv + gb1.y + x1.y;
    v[6] = acc[6] * inv + gb1.z + x1.z;
    v[7] = acc[7] * inv + gb1.w + x1.w;

    // in-warp LayerNorm over the 256-col row
    float s = 0.f, sq = 0.f;
#pragma unroll
    for (int j = 0; j < 8; j++) { s += v[j]; sq += v[j] * v[j]; }
#pragma unroll
    for (int o = 16; o > 0; o >>= 1) {
        s += __shfl_xor_sync(0xffffffffu, s, o);
        sq += __shfl_xor_sync(0xffffffffu, sq, o);
    }
    float mu = s * (1.f / HIDc);
    float var = sq * (1.f / HIDc) - mu * mu;
    float rs = rsqrtf(var + EPSV);

    const float4* lg4 = (const float4*)lng + lane * 2;
    const float4* lb4 = (const float4*)lnb + lane * 2;
    float4 lg0 = lg4[0], lg1 = lg4[1];
    float4 lb0 = lb4[0], lb1 = lb4[1];
    float4 o0, o1;
    o0.x = (v[0] - mu) * rs * lg0.x + lb0.x;
    o0.y = (v[1] - mu) * rs * lg0.y + lb0.y;
    o0.z = (v[2] - mu) * rs * lg0.z + lb0.z;
    o0.w = (v[3] - mu) * rs * lg0.w + lb0.w;
    o1.x = (v[4] - mu) * rs * lg1.x + lb1.x;
    o1.y = (v[5] - mu) * rs * lg1.y + lb1.y;
    o1.z = (v[6] - mu) * rs * lg1.z + lb1.z;
    o1.w = (v[7] - mu) * rs * lg1.w + lb1.w;
    xrow[0] = o0;
    xrow[1] = o1;
}

// ---------------- input LN (once, after proj) ----------------------------
__device__ __forceinline__ void block_mean_var_256(float v, float* smem, float& mu, float& var) {
    float s = v, sq = v * v;
#pragma unroll
    for (int o = 16; o > 0; o >>= 1) {
        s += __shfl_xor_sync(0xffffffffu, s, o);
        sq += __shfl_xor_sync(0xffffffffu, sq, o);
    }
    int w = threadIdx.x >> 5, l = threadIdx.x & 31;
    if (l == 0) { smem[w] = s; smem[8 + w] = sq; }
    __syncthreads();
    if (w == 0) {
        s = (l < 8) ? smem[l] : 0.f;
        sq = (l < 8) ? smem[8 + l] : 0.f;
#pragma unroll
        for (int o = 4; o > 0; o >>= 1) {
            s += __shfl_xor_sync(0xffffffffu, s, o);
            sq += __shfl_xor_sync(0xffffffffu, sq, o);
        }
        if (l == 0) { smem[0] = s; smem[8] = sq; }
    }
    __syncthreads();
    mu = smem[0] * (1.f / HIDc);
    var = smem[8] * (1.f / HIDc) - mu * mu;
}

__global__ void ln_kernel(const float* __restrict__ in, const float* __restrict__ g,
                          const float* __restrict__ b, float* __restrict__ out) {
    __shared__ float smem[16];
    int n = blockIdx.x, c = threadIdx.x;
    float v = in[(size_t)n * HIDc + c];
    float mu, var;
    block_mean_var_256(v, smem, mu, var);
    out[(size_t)n * HIDc + c] = (v - mu) * rsqrtf(var + EPSV) * g[c] + b[c];
}

// ---------------- head: GELU(T) @ h2_W + h2_b, warp per node -------------
__global__ void head2_kernel(const float* __restrict__ T, const float* __restrict__ W2,
                             const float* __restrict__ b2, float* __restrict__ out) {
    int n = blockIdx.x * 8 + (threadIdx.x >> 5);
    if (n >= Nn) return;
    int lane = threadIdx.x & 31;
    const float* t = T + (size_t)n * HIDc;
    float a0 = 0.f, a1 = 0.f, a2 = 0.f;
#pragma unroll
    for (int j = 0; j < 8; j++) {
        int k = j * 32 + lane;
        float x = t[k];
        float ge = 0.5f * x * (1.f + erff(x * 0.70710678118654752440f));
        a0 += ge * W2[k * 3 + 0];
        a1 += ge * W2[k * 3 + 1];
        a2 += ge * W2[k * 3 + 2];
    }
#pragma unroll
    for (int o = 16; o > 0; o >>= 1) {
        a0 += __shfl_xor_sync(0xffffffffu, a0, o);
        a1 += __shfl_xor_sync(0xffffffffu, a1, o);
        a2 += __shfl_xor_sync(0xffffffffu, a2, o);
    }
    if (lane == 0) {
        out[n * 3 + 0] = a0 + b2[0];
        out[n * 3 + 1] = a1 + b2[1];
        out[n * 3 + 2] = a2 + b2[2];
    }
}

// ---------------- launcher ----------------
extern "C" void kernel_launch(void* const* d_in, const int* in_sizes, int n_in,
                              void* d_out, int out_size) {
    const float* features = (const float*)d_in[0];
    const void* ei = d_in[1];
    const float* proj_W = (const float*)d_in[2];
    const float* proj_b = (const float*)d_in[3];
    const float* n0_g = (const float*)d_in[4];
    const float* n0_b = (const float*)d_in[5];
    const float* Wl = (const float*)d_in[6];
    const float* bl = (const float*)d_in[7];
    const float* Wr = (const float*)d_in[8];
    const float* br = (const float*)d_in[9];
    const float* att = (const float*)d_in[10];
    const float* gbias = (const float*)d_in[11];
    const float* ln_g = (const float*)d_in[12];
    const float* ln_b = (const float*)d_in[13];
    const float* h1_W = (const float*)d_in[14];
    const float* h1_b = (const float*)d_in[15];
    const float* h2_W = (const float*)d_in[16];
    const float* h2_b = (const float*)d_in[17];
    float* out = (float*)d_out;

    int E = in_sizes[1] / 2;

    float *pX, *pTmp, *pXL, *pXR;
    cudaGetSymbolAddress((void**)&pX, g_X);
    cudaGetSymbolAddress((void**)&pTmp, g_tmp);
    cudaGetSymbolAddress((void**)&pXL, g_XL);
    cudaGetSymbolAddress((void**)&pXR, g_XR);

    // unconditional (no static guards — harness rule); idempotent host-side set
    cudaFuncSetAttribute(gemm_tc_kernel,
                         cudaFuncAttributeMaxDynamicSharedMemorySize, GEMM_SMEM);

    dim3 g1((Nn + 127) / 128, HIDc / 128, 1);
    dim3 g2((Nn + 127) / 128, HIDc / 128, 2);
    int nodeWarpBlocks = (Nn + 7) / 8;

    detect_idx_kernel<<<1, 32>>>(ei);

    // CSR build
    deg_zero_kernel<<<(Nn + 255) / 256, 256>>>();
    hist_kernel<<<(E + 255) / 256, 256>>>(ei, E);
    scan_kernel<<<1, 1024>>>();
    fill_kernel<<<(E + 255) / 256, 256>>>(ei, E);

    // proj + input LN
    gemm_tc_kernel<<<g1, 256, GEMM_SMEM>>>(features, proj_W, proj_W, proj_b, proj_b,
                                           pTmp, pTmp, Nn, IN_DIMc, HIDc);
    ln_kernel<<<Nn, 256>>>(pTmp, n0_g, n0_b, pX);

    for (int h = 0; h < HOPSc; h++) {
        const float* Wlh = Wl + (size_t)h * HIDc * HIDc;
        const float* Wrh = Wr + (size_t)h * HIDc * HIDc;
        gemm_tc_kernel<<<g2, 256, GEMM_SMEM>>>(pX, Wlh, Wrh, bl + h * HIDc, br + h * HIDc,
                                               pXL, pXR, Nn, HIDc, HIDc);
        edge_agg_kernel<<<nodeWarpBlocks, 256>>>(pXL, pXR, att + h * HEADSc * HDc,
                                                 gbias + h * HIDc,
                                                 ln_g + h * HIDc, ln_b + h * HIDc, pX);
    }

    // head
    gemm_tc_kernel<<<g1, 256, GEMM_SMEM>>>(pX, h1_W, h1_W, h1_b, h1_b,
                                           pTmp, pTmp, Nn, HIDc, HIDc);
    head2_kernel<<<(Nn + 7) / 8, 256>>>(pTmp, h2_W, h2_b, out);
}

// round 13
// speedup vs baseline: 5.1385x; 1.0463x over previous
#include <cuda_runtime.h>
#include <math.h>
#include <stdint.h>

#define Nn 20000
#define IN_DIMc 1536
#define HIDc 256
#define HEADSc 4
#define HDc 64
#define HOPSc 3
#define NCLSc 3
#define EMAXc 400000
#define EPSV 1e-5f
#define NEG_SLOPE 0.2f

// ---------------- scratch (device globals; no allocations) ----------------
__device__ float g_X[Nn * HIDc];
__device__ float g_tmp[Nn * HIDc];
__device__ float g_XL[Nn * HIDc];
__device__ float g_XR[Nn * HIDc];
__device__ int g_deg[Nn];
__device__ int g_rowptr[Nn + 1];
__device__ int g_cursor[Nn];
__device__ int g_esrc[EMAXc];
__device__ int g_flag;  // 1 = edge_index is int64, 0 = int32

// ---------------- dtype probe ----------------
__global__ void detect_idx_kernel(const void* __restrict__ ei) {
    if (threadIdx.x == 0 && blockIdx.x == 0) {
        const long long* p = (const long long*)ei;
        int ok = 1;
        for (int i = 0; i < 256; i++) {
            long long v = p[i];
            if (v < 0 || v >= (long long)Nn) { ok = 0; break; }
        }
        g_flag = ok;
    }
}

__device__ __forceinline__ int edge_get(const void* ei, long long idx, int flag) {
    return flag ? (int)((const long long*)ei)[idx] : ((const int*)ei)[idx];
}

// ---------------- CSR build (once per launch; edges are hop-invariant) ----
__global__ void deg_zero_kernel() {
    int i = blockIdx.x * blockDim.x + threadIdx.x;
    if (i < Nn) g_deg[i] = 0;
}

__global__ void hist_kernel(const void* __restrict__ ei, int E) {
    int e = blockIdx.x * blockDim.x + threadIdx.x;
    if (e >= E) return;
    int dst = edge_get(ei, (long long)E + e, g_flag);
    atomicAdd(&g_deg[dst], 1);
}

// single block, 1024 threads, 20 elems/thread sequential + warp/block scan.
__global__ void scan_kernel() {
    const int PER = 20;  // 1024*20 = 20480 >= Nn
    __shared__ int wsum[32];
    __shared__ int wexcl[32];
    int tid = threadIdx.x, lane = tid & 31, wid = tid >> 5;
    int base = tid * PER;

    int deg[PER];
    int tot = 0;
#pragma unroll
    for (int i = 0; i < PER; i++) {
        int idx = base + i;
        deg[i] = (idx < Nn) ? g_deg[idx] : 0;
        tot += deg[i];
    }
    // warp inclusive scan of per-thread totals
    int incl = tot;
#pragma unroll
    for (int o = 1; o < 32; o <<= 1) {
        int t = __shfl_up_sync(0xffffffffu, incl, o);
        if (lane >= o) incl += t;
    }
    if (lane == 31) wsum[wid] = incl;
    __syncthreads();
    if (wid == 0) {
        int v = wsum[lane];
        int s = v;
#pragma unroll
        for (int o = 1; o < 32; o <<= 1) {
            int t = __shfl_up_sync(0xffffffffu, s, o);
            if (lane >= o) s += t;
        }
        wexcl[lane] = s - v;
    }
    __syncthreads();

    int running = wexcl[wid] + (incl - tot);  // exclusive prefix for this thread
#pragma unroll
    for (int i = 0; i < PER; i++) {
        int idx = base + i;
        if (idx < Nn) {
            g_cursor[idx] = running;
            running += deg[i];
            g_rowptr[idx + 1] = running;
        }
    }
    if (tid == 0) g_rowptr[0] = 0;
}

__global__ void fill_kernel(const void* __restrict__ ei, int E) {
    int e = blockIdx.x * blockDim.x + threadIdx.x;
    if (e >= E) return;
    int flag = g_flag;
    int src = edge_get(ei, e, flag);
    int dst = edge_get(ei, (long long)E + e, flag);
    int pos = atomicAdd(&g_cursor[dst], 1);
    g_esrc[pos] = src;
}

// ---------------- TF32 tensor-core GEMM (3-stage cp.async pipeline) ------
__device__ __forceinline__ uint32_t cvt_tf32(uint32_t bits) {
    float f = __uint_as_float(bits);
    uint32_t r;
    asm("cvt.rna.tf32.f32 %0, %1;" : "=r"(r) : "f"(f));
    return r;
}

__device__ __forceinline__ void mma_tf32(float* c, uint32_t a0, uint32_t a1,
                                         uint32_t a2, uint32_t a3,
                                         uint32_t b0, uint32_t b1) {
    asm volatile(
        "mma.sync.aligned.m16n8k8.row.col.f32.tf32.tf32.f32 "
        "{%0,%1,%2,%3}, {%4,%5,%6,%7}, {%8,%9}, {%0,%1,%2,%3};"
        : "+f"(c[0]), "+f"(c[1]), "+f"(c[2]), "+f"(c[3])
        : "r"(a0), "r"(a1), "r"(a2), "r"(a3), "r"(b0), "r"(b1));
}

__device__ __forceinline__ void cp16(uint32_t saddr, const float* gptr) {
    asm volatile("cp.async.ca.shared.global [%0], [%1], 16;" ::"r"(saddr), "l"(gptr));
}

#define ASTRIDE 20
#define BSTRIDE 136
#define AWORDS (128 * ASTRIDE)
#define BWORDS (16 * BSTRIDE)
#define GEMM_SMEM (3 * (AWORDS + BWORDS) * 4)

__global__ __launch_bounds__(256, 2)
void gemm_tc_kernel(const float* __restrict__ A,
                    const float* __restrict__ B0, const float* __restrict__ B1,
                    const float* __restrict__ bias0, const float* __restrict__ bias1,
                    float* __restrict__ C0, float* __restrict__ C1,
                    int M, int K, int Nc) {
    const float* __restrict__ B = blockIdx.z ? B1 : B0;
    const float* __restrict__ bias = blockIdx.z ? bias1 : bias0;
    float* __restrict__ C = blockIdx.z ? C1 : C0;

    extern __shared__ __align__(16) uint32_t dyn[];
    uint32_t* Asm = dyn;                 // [3][128][ASTRIDE]
    uint32_t* Bsm = dyn + 3 * AWORDS;    // [3][16][BSTRIDE]

    int tid = threadIdx.x;
    int rm = blockIdx.x * 128, cn = blockIdx.y * 128;

    int ar0 = tid >> 2, aq = (tid & 3) * 4;
    int ar1 = ar0 + 64;
    const float* ga0 = A + (size_t)min(rm + ar0, M - 1) * K + aq;
    const float* ga1 = A + (size_t)min(rm + ar1, M - 1) * K + aq;
    int bk0 = tid >> 5, bq = (tid & 31) * 4;
    int bk1 = bk0 + 8;
    const float* gb0 = B + (size_t)bk0 * Nc + cn + bq;
    const float* gb1 = B + (size_t)bk1 * Nc + cn + bq;

    uint32_t sA0[3], sA1[3], sB0[3], sB1[3];
#pragma unroll
    for (int s = 0; s < 3; s++) {
        sA0[s] = (uint32_t)__cvta_generic_to_shared(Asm + s * AWORDS + ar0 * ASTRIDE + aq);
        sA1[s] = (uint32_t)__cvta_generic_to_shared(Asm + s * AWORDS + ar1 * ASTRIDE + aq);
        sB0[s] = (uint32_t)__cvta_generic_to_shared(Bsm + s * BWORDS + bk0 * BSTRIDE + bq);
        sB1[s] = (uint32_t)__cvta_generic_to_shared(Bsm + s * BWORDS + bk1 * BSTRIDE + bq);
    }

    int warp = tid >> 5, lane = tid & 31, grp = lane >> 2, qid = lane & 3;
    int wm = (warp & 3) * 32, wn = (warp >> 2) * 64;

    float acc[2][8][4];
#pragma unroll
    for (int mt = 0; mt < 2; mt++)
#pragma unroll
        for (int nt = 0; nt < 8; nt++)
#pragma unroll
            for (int i = 0; i < 4; i++) acc[mt][nt][i] = 0.f;

    int ntile = K / 16;

    // prologue: stages 0,1
#pragma unroll
    for (int p = 0; p < 2; p++) {
        if (p < ntile) {
            int kt = p * 16;
            cp16(sA0[p], ga0 + kt);
            cp16(sA1[p], ga1 + kt);
            cp16(sB0[p], gb0 + (size_t)kt * Nc);
            cp16(sB1[p], gb1 + (size_t)kt * Nc);
        }
        asm volatile("cp.async.commit_group;");
    }

    int stage = 0;
    for (int t = 0; t < ntile; t++) {
        if (t + 2 < ntile) {
            int kt = (t + 2) * 16;
            int ps = (stage + 2) % 3;
            cp16(sA0[ps], ga0 + kt);
            cp16(sA1[ps], ga1 + kt);
            cp16(sB0[ps], gb0 + (size_t)kt * Nc);
            cp16(sB1[ps], gb1 + (size_t)kt * Nc);
            asm volatile("cp.async.commit_group;");
            asm volatile("cp.async.wait_group 2;");
        } else if (t + 1 < ntile) {
            asm volatile("cp.async.wait_group 1;");
        } else {
            asm volatile("cp.async.wait_group 0;");
        }
        __syncthreads();

        const uint32_t* As = Asm + stage * AWORDS;
        const uint32_t* Bs = Bsm + stage * BWORDS;
#pragma unroll
        for (int ks = 0; ks < 16; ks += 8) {
            uint32_t af[2][4];
#pragma unroll
            for (int mt = 0; mt < 2; mt++) {
                int m = wm + mt * 16 + grp;
                af[mt][0] = cvt_tf32(As[m * ASTRIDE + ks + qid]);
                af[mt][1] = cvt_tf32(As[(m + 8) * ASTRIDE + ks + qid]);
                af[mt][2] = cvt_tf32(As[m * ASTRIDE + ks + qid + 4]);
                af[mt][3] = cvt_tf32(As[(m + 8) * ASTRIDE + ks + qid + 4]);
            }
#pragma unroll
            for (int nt = 0; nt < 8; nt++) {
                int n = wn + nt * 8 + grp;
                uint32_t b0 = cvt_tf32(Bs[(ks + qid) * BSTRIDE + n]);
                uint32_t b1 = cvt_tf32(Bs[(ks + qid + 4) * BSTRIDE + n]);
                mma_tf32(acc[0][nt], af[0][0], af[0][1], af[0][2], af[0][3], b0, b1);
                mma_tf32(acc[1][nt], af[1][0], af[1][1], af[1][2], af[1][3], b0, b1);
            }
        }
        __syncthreads();
        stage = (stage + 1) % 3;
    }

#pragma unroll
    for (int nt = 0; nt < 8; nt++) {
        int gcol = cn + wn + nt * 8 + qid * 2;
        float2 bb = *(const float2*)(bias + gcol);
#pragma unroll
        for (int mt = 0; mt < 2; mt++) {
            int r0 = rm + wm + mt * 16 + grp;
            int r1 = r0 + 8;
            if (r0 < M) {
                float2 o = make_float2(acc[mt][nt][0] + bb.x, acc[mt][nt][1] + bb.y);
                *(float2*)(C + (size_t)r0 * Nc + gcol) = o;
            }
            if (r1 < M) {
                float2 o = make_float2(acc[mt][nt][2] + bb.x, acc[mt][nt][3] + bb.y);
                *(float2*)(C + (size_t)r1 * Nc + gcol) = o;
            }
        }
    }
}

// ---------------- fused edge aggregation + bias/residual/LN --------------
__global__ __launch_bounds__(256)
void edge_agg_kernel(const float* __restrict__ XL, const float* __restrict__ XR,
                     const float* __restrict__ att,
                     const float* __restrict__ gbias,
                     const float* __restrict__ lng, const float* __restrict__ lnb,
                     float* __restrict__ X) {
    int n = blockIdx.x * 8 + (threadIdx.x >> 5);
    if (n >= Nn) return;
    int lane = threadIdx.x & 31;

    const float4* xr4 = (const float4*)(XR + (size_t)n * HIDc) + lane * 2;
    const float4* at4 = (const float4*)att + lane * 2;
    float4 xr0 = xr4[0], xr1 = xr4[1];
    float4 at0 = at4[0], at1 = at4[1];

    float m = -1e30f, d = 0.f;
    float acc[8];
#pragma unroll
    for (int j = 0; j < 8; j++) acc[j] = 0.f;

    int beg = g_rowptr[n], end = g_rowptr[n + 1];
    for (int e = beg; e <= end; e++) {
        int src = (e < end) ? __ldg(&g_esrc[e]) : n;  // self loop last
        const float4* xl4 = (const float4*)(XL + (size_t)src * HIDc) + lane * 2;
        float4 a0 = xl4[0], a1 = xl4[1];

        float s, v;
        v = a0.x + xr0.x; v = v > 0.f ? v : NEG_SLOPE * v; s  = v * at0.x;
        v = a0.y + xr0.y; v = v > 0.f ? v : NEG_SLOPE * v; s += v * at0.y;
        v = a0.z + xr0.z; v = v > 0.f ? v : NEG_SLOPE * v; s += v * at0.z;
        v = a0.w + xr0.w; v = v > 0.f ? v : NEG_SLOPE * v; s += v * at0.w;
        v = a1.x + xr1.x; v = v > 0.f ? v : NEG_SLOPE * v; s += v * at1.x;
        v = a1.y + xr1.y; v = v > 0.f ? v : NEG_SLOPE * v; s += v * at1.y;
        v = a1.z + xr1.z; v = v > 0.f ? v : NEG_SLOPE * v; s += v * at1.z;
        v = a1.w + xr1.w; v = v > 0.f ? v : NEG_SLOPE * v; s += v * at1.w;
        s += __shfl_xor_sync(0xffffffffu, s, 1);
        s += __shfl_xor_sync(0xffffffffu, s, 2);
        s += __shfl_xor_sync(0xffffffffu, s, 4);

        float nm = fmaxf(m, s);
        float sc = __expf(m - nm);
        float w = __expf(s - nm);
        d = d * sc + w;
        acc[0] = acc[0] * sc + w * a0.x;
        acc[1] = acc[1] * sc + w * a0.y;
        acc[2] = acc[2] * sc + w * a0.z;
        acc[3] = acc[3] * sc + w * a0.w;
        acc[4] = acc[4] * sc + w * a1.x;
        acc[5] = acc[5] * sc + w * a1.y;
        acc[6] = acc[6] * sc + w * a1.z;
        acc[7] = acc[7] * sc + w * a1.w;
        m = nm;
    }

    float inv = 1.f / d;
    float4* xrow = (float4*)(X + (size_t)n * HIDc) + lane * 2;
    float4 x0 = xrow[0], x1 = xrow[1];
    const float4* gb4 = (const float4*)gbias + lane * 2;
    float4 gb0 = gb4[0], gb1 = gb4[1];
    float v[8];
    v[0] = acc[0] * inv + gb0.x + x0.x;
    v[1] = acc[1] * inv + gb0.y + x0.y;
    v[2] = acc[2] * inv + gb0.z + x0.z;
    v[3] = acc[3] * inv + gb0.w + x0.w;
    v[4] = acc[4] * inv + gb1.x + x1.x;
    v[5] = acc[5] * inv + gb1.y + x1.y;
    v[6] = acc[6] * inv + gb1.z + x1.z;
    v[7] = acc[7] * inv + gb1.w + x1.w;

    float s = 0.f, sq = 0.f;
#pragma unroll
    for (int j = 0; j < 8; j++) { s += v[j]; sq += v[j] * v[j]; }
#pragma unroll
    for (int o = 16; o > 0; o >>= 1) {
        s += __shfl_xor_sync(0xffffffffu, s, o);
        sq += __shfl_xor_sync(0xffffffffu, sq, o);
    }
    float mu = s * (1.f / HIDc);
    float var = sq * (1.f / HIDc) - mu * mu;
    float rs = rsqrtf(var + EPSV);

    const float4* lg4 = (const float4*)lng + lane * 2;
    const float4* lb4 = (const float4*)lnb + lane * 2;
    float4 lg0 = lg4[0], lg1 = lg4[1];
    float4 lb0 = lb4[0], lb1 = lb4[1];
    float4 o0, o1;
    o0.x = (v[0] - mu) * rs * lg0.x + lb0.x;
    o0.y = (v[1] - mu) * rs * lg0.y + lb0.y;
    o0.z = (v[2] - mu) * rs * lg0.z + lb0.z;
    o0.w = (v[3] - mu) * rs * lg0.w + lb0.w;
    o1.x = (v[4] - mu) * rs * lg1.x + lb1.x;
    o1.y = (v[5] - mu) * rs * lg1.y + lb1.y;
    o1.z = (v[6] - mu) * rs * lg1.z + lb1.z;
    o1.w = (v[7] - mu) * rs * lg1.w + lb1.w;
    xrow[0] = o0;
    xrow[1] = o1;
}

// ---------------- input LN (once, after proj) ----------------------------
__device__ __forceinline__ void block_mean_var_256(float v, float* smem, float& mu, float& var) {
    float s = v, sq = v * v;
#pragma unroll
    for (int o = 16; o > 0; o >>= 1) {
        s += __shfl_xor_sync(0xffffffffu, s, o);
        sq += __shfl_xor_sync(0xffffffffu, sq, o);
    }
    int w = threadIdx.x >> 5, l = threadIdx.x & 31;
    if (l == 0) { smem[w] = s; smem[8 + w] = sq; }
    __syncthreads();
    if (w == 0) {
        s = (l < 8) ? smem[l] : 0.f;
        sq = (l < 8) ? smem[8 + l] : 0.f;
#pragma unroll
        for (int o = 4; o > 0; o >>= 1) {
            s += __shfl_xor_sync(0xffffffffu, s, o);
            sq += __shfl_xor_sync(0xffffffffu, sq, o);
        }
        if (l == 0) { smem[0] = s; smem[8] = sq; }
    }
    __syncthreads();
    mu = smem[0] * (1.f / HIDc);
    var = smem[8] * (1.f / HIDc) - mu * mu;
}

__global__ void ln_kernel(const float* __restrict__ in, const float* __restrict__ g,
                          const float* __restrict__ b, float* __restrict__ out) {
    __shared__ float smem[16];
    int n = blockIdx.x, c = threadIdx.x;
    float v = in[(size_t)n * HIDc + c];
    float mu, var;
    block_mean_var_256(v, smem, mu, var);
    out[(size_t)n * HIDc + c] = (v - mu) * rsqrtf(var + EPSV) * g[c] + b[c];
}

// ---------------- head: GELU(T) @ h2_W + h2_b, warp per node -------------
__global__ void head2_kernel(const float* __restrict__ T, const float* __restrict__ W2,
                             const float* __restrict__ b2, float* __restrict__ out) {
    int n = blockIdx.x * 8 + (threadIdx.x >> 5);
    if (n >= Nn) return;
    int lane = threadIdx.x & 31;
    const float* t = T + (size_t)n * HIDc;
    float a0 = 0.f, a1 = 0.f, a2 = 0.f;
#pragma unroll
    for (int j = 0; j < 8; j++) {
        int k = j * 32 + lane;
        float x = t[k];
        float ge = 0.5f * x * (1.f + erff(x * 0.70710678118654752440f));
        a0 += ge * W2[k * 3 + 0];
        a1 += ge * W2[k * 3 + 1];
        a2 += ge * W2[k * 3 + 2];
    }
#pragma unroll
    for (int o = 16; o > 0; o >>= 1) {
        a0 += __shfl_xor_sync(0xffffffffu, a0, o);
        a1 += __shfl_xor_sync(0xffffffffu, a1, o);
        a2 += __shfl_xor_sync(0xffffffffu, a2, o);
    }
    if (lane == 0) {
        out[n * 3 + 0] = a0 + b2[0];
        out[n * 3 + 1] = a1 + b2[1];
        out[n * 3 + 2] = a2 + b2[2];
    }
}

// ---------------- launcher ----------------
extern "C" void kernel_launch(void* const* d_in, const int* in_sizes, int n_in,
                              void* d_out, int out_size) {
    const float* features = (const float*)d_in[0];
    const void* ei = d_in[1];
    const float* proj_W = (const float*)d_in[2];
    const float* proj_b = (const float*)d_in[3];
    const float* n0_g = (const float*)d_in[4];
    const float* n0_b = (const float*)d_in[5];
    const float* Wl = (const float*)d_in[6];
    const float* bl = (const float*)d_in[7];
    const float* Wr = (const float*)d_in[8];
    const float* br = (const float*)d_in[9];
    const float* att = (const float*)d_in[10];
    const float* gbias = (const float*)d_in[11];
    const float* ln_g = (const float*)d_in[12];
    const float* ln_b = (const float*)d_in[13];
    const float* h1_W = (const float*)d_in[14];
    const float* h1_b = (const float*)d_in[15];
    const float* h2_W = (const float*)d_in[16];
    const float* h2_b = (const float*)d_in[17];
    float* out = (float*)d_out;

    int E = in_sizes[1] / 2;

    float *pX, *pTmp, *pXL, *pXR;
    cudaGetSymbolAddress((void**)&pX, g_X);
    cudaGetSymbolAddress((void**)&pTmp, g_tmp);
    cudaGetSymbolAddress((void**)&pXL, g_XL);
    cudaGetSymbolAddress((void**)&pXR, g_XR);

    cudaFuncSetAttribute(gemm_tc_kernel,
                         cudaFuncAttributeMaxDynamicSharedMemorySize, GEMM_SMEM);

    dim3 g1((Nn + 127) / 128, HIDc / 128, 1);
    dim3 g2((Nn + 127) / 128, HIDc / 128, 2);
    int nodeWarpBlocks = (Nn + 7) / 8;

    // side stream for the CSR build, overlapped with the proj GEMM.
    cudaStream_t s2;
    cudaStreamCreateWithFlags(&s2, cudaStreamNonBlocking);
    cudaEvent_t evFork, evJoin;
    cudaEventCreateWithFlags(&evFork, cudaEventDisableTiming);
    cudaEventCreateWithFlags(&evJoin, cudaEventDisableTiming);

    detect_idx_kernel<<<1, 32>>>(ei);
    cudaEventRecord(evFork, 0);
    cudaStreamWaitEvent(s2, evFork, 0);

    // CSR build on s2 (needs only g_flag)
    deg_zero_kernel<<<(Nn + 255) / 256, 256, 0, s2>>>();
    hist_kernel<<<(E + 255) / 256, 256, 0, s2>>>(ei, E);
    scan_kernel<<<1, 1024, 0, s2>>>();
    fill_kernel<<<(E + 255) / 256, 256, 0, s2>>>(ei, E);
    cudaEventRecord(evJoin, s2);

    // proj + input LN on main stream (independent of CSR)
    gemm_tc_kernel<<<g1, 256, GEMM_SMEM>>>(features, proj_W, proj_W, proj_b, proj_b,
                                           pTmp, pTmp, Nn, IN_DIMc, HIDc);
    ln_kernel<<<Nn, 256>>>(pTmp, n0_g, n0_b, pX);

    // join: hop loop needs rowptr/esrc
    cudaStreamWaitEvent(0, evJoin, 0);

    for (int h = 0; h < HOPSc; h++) {
        const float* Wlh = Wl + (size_t)h * HIDc * HIDc;
        const float* Wrh = Wr + (size_t)h * HIDc * HIDc;
        gemm_tc_kernel<<<g2, 256, GEMM_SMEM>>>(pX, Wlh, Wrh, bl + h * HIDc, br + h * HIDc,
                                               pXL, pXR, Nn, HIDc, HIDc);
        edge_agg_kernel<<<nodeWarpBlocks, 256>>>(pXL, pXR, att + h * HEADSc * HDc,
                                                 gbias + h * HIDc,
                                                 ln_g + h * HIDc, ln_b + h * HIDc, pX);
    }

    // head
    gemm_tc_kernel<<<g1, 256, GEMM_SMEM>>>(pX, h1_W, h1_W, h1_b, h1_b,
                                           pTmp, pTmp, Nn, HIDc, HIDc);
    head2_kernel<<<(Nn + 7) / 8, 256>>>(pTmp, h2_W, h2_b, out);

    cudaEventDestroy(evFork);
    cudaEventDestroy(evJoin);
    cudaStreamDestroy(s2);
}

// round 14
// speedup vs baseline: 5.7836x; 1.1255x over previous
#include <cuda_runtime.h>
#include <math.h>
#include <stdint.h>

#define Nn 20000
#define IN_DIMc 1536
#define HIDc 256
#define HEADSc 4
#define HDc 64
#define HOPSc 3
#define NCLSc 3
#define EMAXc 400000
#define EPSV 1e-5f
#define NEG_SLOPE 0.2f

// ---------------- scratch (device globals; no allocations) ----------------
__device__ float g_X[Nn * HIDc];
__device__ float g_tmp[Nn * HIDc];
__device__ float g_XL[Nn * HIDc];
__device__ float g_XR[Nn * HIDc];
__device__ int g_deg[Nn];
__device__ int g_rowptr[Nn + 1];
__device__ int g_cursor[Nn];
__device__ int g_esrc[EMAXc];
__device__ int g_flag;  // 1 = edge_index is int64, 0 = int32
// tf32-pre-rounded weights (cvt.rna applied once; bit-identical to in-loop cvt)
__device__ float g_cprojW[IN_DIMc * HIDc];
__device__ float g_cWl[HOPSc * HIDc * HIDc];
__device__ float g_cWr[HOPSc * HIDc * HIDc];
__device__ float g_ch1W[HIDc * HIDc];

// ---------------- dtype probe ----------------
__global__ void detect_idx_kernel(const void* __restrict__ ei) {
    if (threadIdx.x == 0 && blockIdx.x == 0) {
        const long long* p = (const long long*)ei;
        int ok = 1;
        for (int i = 0; i < 256; i++) {
            long long v = p[i];
            if (v < 0 || v >= (long long)Nn) { ok = 0; break; }
        }
        g_flag = ok;
    }
}

__device__ __forceinline__ int edge_get(const void* ei, long long idx, int flag) {
    return flag ? (int)((const long long*)ei)[idx] : ((const int*)ei)[idx];
}

// ---------------- tf32 helpers ----------------
__device__ __forceinline__ uint32_t cvt_tf32(uint32_t bits) {
    float f = __uint_as_float(bits);
    uint32_t r;
    asm("cvt.rna.tf32.f32 %0, %1;" : "=r"(r) : "f"(f));
    return r;
}

// weight pre-rounding pass
__global__ void cvt_w_kernel(const float* __restrict__ src, float* __restrict__ dst, int n) {
    int i = blockIdx.x * blockDim.x + threadIdx.x;
    if (i < n) dst[i] = __uint_as_float(cvt_tf32(__float_as_uint(src[i])));
}

// ---------------- CSR build ----------------
__global__ void deg_zero_kernel() {
    int i = blockIdx.x * blockDim.x + threadIdx.x;
    if (i < Nn) g_deg[i] = 0;
}

__global__ void hist_kernel(const void* __restrict__ ei, int E) {
    int e = blockIdx.x * blockDim.x + threadIdx.x;
    if (e >= E) return;
    int dst = edge_get(ei, (long long)E + e, g_flag);
    atomicAdd(&g_deg[dst], 1);
}

__global__ void scan_kernel() {
    const int PER = 20;  // 1024*20 = 20480 >= Nn
    __shared__ int wsum[32];
    __shared__ int wexcl[32];
    int tid = threadIdx.x, lane = tid & 31, wid = tid >> 5;
    int base = tid * PER;

    int deg[PER];
    int tot = 0;
#pragma unroll
    for (int i = 0; i < PER; i++) {
        int idx = base + i;
        deg[i] = (idx < Nn) ? g_deg[idx] : 0;
        tot += deg[i];
    }
    int incl = tot;
#pragma unroll
    for (int o = 1; o < 32; o <<= 1) {
        int t = __shfl_up_sync(0xffffffffu, incl, o);
        if (lane >= o) incl += t;
    }
    if (lane == 31) wsum[wid] = incl;
    __syncthreads();
    if (wid == 0) {
        int v = wsum[lane];
        int s = v;
#pragma unroll
        for (int o = 1; o < 32; o <<= 1) {
            int t = __shfl_up_sync(0xffffffffu, s, o);
            if (lane >= o) s += t;
        }
        wexcl[lane] = s - v;
    }
    __syncthreads();

    int running = wexcl[wid] + (incl - tot);
#pragma unroll
    for (int i = 0; i < PER; i++) {
        int idx = base + i;
        if (idx < Nn) {
            g_cursor[idx] = running;
            running += deg[i];
            g_rowptr[idx + 1] = running;
        }
    }
    if (tid == 0) g_rowptr[0] = 0;
}

__global__ void fill_kernel(const void* __restrict__ ei, int E) {
    int e = blockIdx.x * blockDim.x + threadIdx.x;
    if (e >= E) return;
    int flag = g_flag;
    int src = edge_get(ei, e, flag);
    int dst = edge_get(ei, (long long)E + e, flag);
    int pos = atomicAdd(&g_cursor[dst], 1);
    g_esrc[pos] = src;
}

// ---------------- TF32 tensor-core GEMM (BK=32, 2-stage cp.async) --------
// B operands must be pre-rounded tf32 (loaded without cvt).
__device__ __forceinline__ void mma_tf32(float* c, uint32_t a0, uint32_t a1,
                                         uint32_t a2, uint32_t a3,
                                         uint32_t b0, uint32_t b1) {
    asm volatile(
        "mma.sync.aligned.m16n8k8.row.col.f32.tf32.tf32.f32 "
        "{%0,%1,%2,%3}, {%4,%5,%6,%7}, {%8,%9}, {%0,%1,%2,%3};"
        : "+f"(c[0]), "+f"(c[1]), "+f"(c[2]), "+f"(c[3])
        : "r"(a0), "r"(a1), "r"(a2), "r"(a3), "r"(b0), "r"(b1));
}

__device__ __forceinline__ void cp16(uint32_t saddr, const float* gptr) {
    asm volatile("cp.async.ca.shared.global [%0], [%1], 16;" ::"r"(saddr), "l"(gptr));
}

#define BKc 32
#define ASTRIDE 36                    // 32 + 4 pad: conflict-free frag reads
#define BSTRIDE 136                   // 128 + 8 pad
#define AWORDS (128 * ASTRIDE)        // 4608
#define BWORDS (BKc * BSTRIDE)        // 4352
#define GEMM_SMEM (2 * (AWORDS + BWORDS) * 4)   // 71680 B

__global__ __launch_bounds__(256, 2)
void gemm_tc_kernel(const float* __restrict__ A,
                    const float* __restrict__ B0, const float* __restrict__ B1,
                    const float* __restrict__ bias0, const float* __restrict__ bias1,
                    float* __restrict__ C0, float* __restrict__ C1,
                    int M, int K, int Nc) {
    const float* __restrict__ B = blockIdx.z ? B1 : B0;
    const float* __restrict__ bias = blockIdx.z ? bias1 : bias0;
    float* __restrict__ C = blockIdx.z ? C1 : C0;

    extern __shared__ __align__(16) uint32_t dyn[];
    uint32_t* Asm = dyn;                 // [2][128][ASTRIDE]
    uint32_t* Bsm = dyn + 2 * AWORDS;    // [2][BKc][BSTRIDE]

    int tid = threadIdx.x;
    int rm = blockIdx.x * 128, cn = blockIdx.y * 128;

    // A tile 128x32: 1024 float4 chunks; thread handles c = tid + p*256.
    // row = c>>3 (8 chunks/row), colq = (c&7)*4  (col same for all p)
    int arow = tid >> 3, aq = (tid & 7) * 4;
    // B tile 32x128: row = c>>5, colq = (c&31)*4
    int bkr = tid >> 5, bq = (tid & 31) * 4;

    const float* ga[4];
    uint32_t sAa[2][4], sBa[2][4];
#pragma unroll
    for (int p = 0; p < 4; p++) {
        int r = arow + p * 32;
        ga[p] = A + (size_t)min(rm + r, M - 1) * K + aq;
#pragma unroll
        for (int s = 0; s < 2; s++)
            sAa[s][p] = (uint32_t)__cvta_generic_to_shared(Asm + s * AWORDS + r * ASTRIDE + aq);
    }
    const float* gb[4];
#pragma unroll
    for (int p = 0; p < 4; p++) {
        int kr = bkr + p * 8;
        gb[p] = B + (size_t)kr * Nc + cn + bq;
#pragma unroll
        for (int s = 0; s < 2; s++)
            sBa[s][p] = (uint32_t)__cvta_generic_to_shared(Bsm + s * BWORDS + kr * BSTRIDE + bq);
    }

    int warp = tid >> 5, lane = tid & 31, grp = lane >> 2, qid = lane & 3;
    int wm = (warp & 3) * 32, wn = (warp >> 2) * 64;

    float acc[2][8][4];
#pragma unroll
    for (int mt = 0; mt < 2; mt++)
#pragma unroll
        for (int nt = 0; nt < 8; nt++)
#pragma unroll
            for (int i = 0; i < 4; i++) acc[mt][nt][i] = 0.f;

    int ntile = K / BKc;

    // prologue: stage 0
#pragma unroll
    for (int p = 0; p < 4; p++) {
        cp16(sAa[0][p], ga[p]);
        cp16(sBa[0][p], gb[p]);
    }
    asm volatile("cp.async.commit_group;");

    int s = 0;
    for (int t = 0; t < ntile; t++) {
        if (t + 1 < ntile) {
            int kt = (t + 1) * BKc;
#pragma unroll
            for (int p = 0; p < 4; p++) {
                cp16(sAa[s ^ 1][p], ga[p] + kt);
                cp16(sBa[s ^ 1][p], gb[p] + (size_t)kt * Nc);
            }
            asm volatile("cp.async.commit_group;");
            asm volatile("cp.async.wait_group 1;");
        } else {
            asm volatile("cp.async.wait_group 0;");
        }
        __syncthreads();

        const uint32_t* As = Asm + s * AWORDS;
        const uint32_t* Bs = Bsm + s * BWORDS;
#pragma unroll
        for (int ks = 0; ks < BKc; ks += 8) {
            uint32_t af[2][4];
#pragma unroll
            for (int mt = 0; mt < 2; mt++) {
                int m = wm + mt * 16 + grp;
                af[mt][0] = cvt_tf32(As[m * ASTRIDE + ks + qid]);
                af[mt][1] = cvt_tf32(As[(m + 8) * ASTRIDE + ks + qid]);
                af[mt][2] = cvt_tf32(As[m * ASTRIDE + ks + qid + 4]);
                af[mt][3] = cvt_tf32(As[(m + 8) * ASTRIDE + ks + qid + 4]);
            }
#pragma unroll
            for (int nt = 0; nt < 8; nt++) {
                int n = wn + nt * 8 + grp;
                uint32_t b0 = Bs[(ks + qid) * BSTRIDE + n];       // pre-rounded tf32
                uint32_t b1 = Bs[(ks + qid + 4) * BSTRIDE + n];
                mma_tf32(acc[0][nt], af[0][0], af[0][1], af[0][2], af[0][3], b0, b1);
                mma_tf32(acc[1][nt], af[1][0], af[1][1], af[1][2], af[1][3], b0, b1);
            }
        }
        __syncthreads();
        s ^= 1;
    }

#pragma unroll
    for (int nt = 0; nt < 8; nt++) {
        int gcol = cn + wn + nt * 8 + qid * 2;
        float2 bb = *(const float2*)(bias + gcol);
#pragma unroll
        for (int mt = 0; mt < 2; mt++) {
            int r0 = rm + wm + mt * 16 + grp;
            int r1 = r0 + 8;
            if (r0 < M) {
                float2 o = make_float2(acc[mt][nt][0] + bb.x, acc[mt][nt][1] + bb.y);
                *(float2*)(C + (size_t)r0 * Nc + gcol) = o;
            }
            if (r1 < M) {
                float2 o = make_float2(acc[mt][nt][2] + bb.x, acc[mt][nt][3] + bb.y);
                *(float2*)(C + (size_t)r1 * Nc + gcol) = o;
            }
        }
    }
}

// ---------------- fused edge aggregation + bias/residual/LN --------------
__global__ __launch_bounds__(256)
void edge_agg_kernel(const float* __restrict__ XL, const float* __restrict__ XR,
                     const float* __restrict__ att,
                     const float* __restrict__ gbias,
                     const float* __restrict__ lng, const float* __restrict__ lnb,
                     float* __restrict__ X) {
    int n = blockIdx.x * 8 + (threadIdx.x >> 5);
    if (n >= Nn) return;
    int lane = threadIdx.x & 31;

    const float4* xr4 = (const float4*)(XR + (size_t)n * HIDc) + lane * 2;
    const float4* at4 = (const float4*)att + lane * 2;
    float4 xr0 = xr4[0], xr1 = xr4[1];
    float4 at0 = at4[0], at1 = at4[1];

    float m = -1e30f, d = 0.f;
    float acc[8];
#pragma unroll
    for (int j = 0; j < 8; j++) acc[j] = 0.f;

    int beg = g_rowptr[n], end = g_rowptr[n + 1];
    for (int e = beg; e <= end; e++) {
        int src = (e < end) ? __ldg(&g_esrc[e]) : n;  // self loop last
        const float4* xl4 = (const float4*)(XL + (size_t)src * HIDc) + lane * 2;
        float4 a0 = xl4[0], a1 = xl4[1];

        float s, v;
        v = a0.x + xr0.x; v = v > 0.f ? v : NEG_SLOPE * v; s  = v * at0.x;
        v = a0.y + xr0.y; v = v > 0.f ? v : NEG_SLOPE * v; s += v * at0.y;
        v = a0.z + xr0.z; v = v > 0.f ? v : NEG_SLOPE * v; s += v * at0.z;
        v = a0.w + xr0.w; v = v > 0.f ? v : NEG_SLOPE * v; s += v * at0.w;
        v = a1.x + xr1.x; v = v > 0.f ? v : NEG_SLOPE * v; s += v * at1.x;
        v = a1.y + xr1.y; v = v > 0.f ? v : NEG_SLOPE * v; s += v * at1.y;
        v = a1.z + xr1.z; v = v > 0.f ? v : NEG_SLOPE * v; s += v * at1.z;
        v = a1.w + xr1.w; v = v > 0.f ? v : NEG_SLOPE * v; s += v * at1.w;
        s += __shfl_xor_sync(0xffffffffu, s, 1);
        s += __shfl_xor_sync(0xffffffffu, s, 2);
        s += __shfl_xor_sync(0xffffffffu, s, 4);

        float nm = fmaxf(m, s);
        float sc = __expf(m - nm);
        float w = __expf(s - nm);
        d = d * sc + w;
        acc[0] = acc[0] * sc + w * a0.x;
        acc[1] = acc[1] * sc + w * a0.y;
        acc[2] = acc[2] * sc + w * a0.z;
        acc[3] = acc[3] * sc + w * a0.w;
        acc[4] = acc[4] * sc + w * a1.x;
        acc[5] = acc[5] * sc + w * a1.y;
        acc[6] = acc[6] * sc + w * a1.z;
        acc[7] = acc[7] * sc + w * a1.w;
        m = nm;
    }

    float inv = 1.f / d;
    float4* xrow = (float4*)(X + (size_t)n * HIDc) + lane * 2;
    float4 x0 = xrow[0], x1 = xrow[1];
    const float4* gb4 = (const float4*)gbias + lane * 2;
    float4 gb0 = gb4[0], gb1 = gb4[1];
    float v[8];
    v[0] = acc[0] * inv + gb0.x + x0.x;
    v[1] = acc[1] * inv + gb0.y + x0.y;
    v[2] = acc[2] * inv + gb0.z + x0.z;
    v[3] = acc[3] * inv + gb0.w + x0.w;
    v[4] = acc[4] * inv + gb1.x + x1.x;
    v[5] = acc[5] * inv + gb1.y + x1.y;
    v[6] = acc[6] * inv + gb1.z + x1.z;
    v[7] = acc[7] * inv + gb1.w + x1.w;

    float s = 0.f, sq = 0.f;
#pragma unroll
    for (int j = 0; j < 8; j++) { s += v[j]; sq += v[j] * v[j]; }
#pragma unroll
    for (int o = 16; o > 0; o >>= 1) {
        s += __shfl_xor_sync(0xffffffffu, s, o);
        sq += __shfl_xor_sync(0xffffffffu, sq, o);
    }
    float mu = s * (1.f / HIDc);
    float var = sq * (1.f / HIDc) - mu * mu;
    float rs = rsqrtf(var + EPSV);

    const float4* lg4 = (const float4*)lng + lane * 2;
    const float4* lb4 = (const float4*)lnb + lane * 2;
    float4 lg0 = lg4[0], lg1 = lg4[1];
    float4 lb0 = lb4[0], lb1 = lb4[1];
    float4 o0, o1;
    o0.x = (v[0] - mu) * rs * lg0.x + lb0.x;
    o0.y = (v[1] - mu) * rs * lg0.y + lb0.y;
    o0.z = (v[2] - mu) * rs * lg0.z + lb0.z;
    o0.w = (v[3] - mu) * rs * lg0.w + lb0.w;
    o1.x = (v[4] - mu) * rs * lg1.x + lb1.x;
    o1.y = (v[5] - mu) * rs * lg1.y + lb1.y;
    o1.z = (v[6] - mu) * rs * lg1.z + lb1.z;
    o1.w = (v[7] - mu) * rs * lg1.w + lb1.w;
    xrow[0] = o0;
    xrow[1] = o1;
}

// ---------------- input LN (once, after proj) ----------------------------
__device__ __forceinline__ void block_mean_var_256(float v, float* smem, float& mu, float& var) {
    float s = v, sq = v * v;
#pragma unroll
    for (int o = 16; o > 0; o >>= 1) {
        s += __shfl_xor_sync(0xffffffffu, s, o);
        sq += __shfl_xor_sync(0xffffffffu, sq, o);
    }
    int w = threadIdx.x >> 5, l = threadIdx.x & 31;
    if (l == 0) { smem[w] = s; smem[8 + w] = sq; }
    __syncthreads();
    if (w == 0) {
        s = (l < 8) ? smem[l] : 0.f;
        sq = (l < 8) ? smem[8 + l] : 0.f;
#pragma unroll
        for (int o = 4; o > 0; o >>= 1) {
            s += __shfl_xor_sync(0xffffffffu, s, o);
            sq += __shfl_xor_sync(0xffffffffu, sq, o);
        }
        if (l == 0) { smem[0] = s; smem[8] = sq; }
    }
    __syncthreads();
    mu = smem[0] * (1.f / HIDc);
    var = smem[8] * (1.f / HIDc) - mu * mu;
}

__global__ void ln_kernel(const float* __restrict__ in, const float* __restrict__ g,
                          const float* __restrict__ b, float* __restrict__ out) {
    __shared__ float smem[16];
    int n = blockIdx.x, c = threadIdx.x;
    float v = in[(size_t)n * HIDc + c];
    float mu, var;
    block_mean_var_256(v, smem, mu, var);
    out[(size_t)n * HIDc + c] = (v - mu) * rsqrtf(var + EPSV) * g[c] + b[c];
}

// ---------------- head: GELU(T) @ h2_W + h2_b, warp per node -------------
__global__ void head2_kernel(const float* __restrict__ T, const float* __restrict__ W2,
                             const float* __restrict__ b2, float* __restrict__ out) {
    int n = blockIdx.x * 8 + (threadIdx.x >> 5);
    if (n >= Nn) return;
    int lane = threadIdx.x & 31;
    const float* t = T + (size_t)n * HIDc;
    float a0 = 0.f, a1 = 0.f, a2 = 0.f;
#pragma unroll
    for (int j = 0; j < 8; j++) {
        int k = j * 32 + lane;
        float x = t[k];
        float ge = 0.5f * x * (1.f + erff(x * 0.70710678118654752440f));
        a0 += ge * W2[k * 3 + 0];
        a1 += ge * W2[k * 3 + 1];
        a2 += ge * W2[k * 3 + 2];
    }
#pragma unroll
    for (int o = 16; o > 0; o >>= 1) {
        a0 += __shfl_xor_sync(0xffffffffu, a0, o);
        a1 += __shfl_xor_sync(0xffffffffu, a1, o);
        a2 += __shfl_xor_sync(0xffffffffu, a2, o);
    }
    if (lane == 0) {
        out[n * 3 + 0] = a0 + b2[0];
        out[n * 3 + 1] = a1 + b2[1];
        out[n * 3 + 2] = a2 + b2[2];
    }
}

// ---------------- launcher ----------------
extern "C" void kernel_launch(void* const* d_in, const int* in_sizes, int n_in,
                              void* d_out, int out_size) {
    const float* features = (const float*)d_in[0];
    const void* ei = d_in[1];
    const float* proj_W = (const float*)d_in[2];
    const float* proj_b = (const float*)d_in[3];
    const float* n0_g = (const float*)d_in[4];
    const float* n0_b = (const float*)d_in[5];
    const float* Wl = (const float*)d_in[6];
    const float* bl = (const float*)d_in[7];
    const float* Wr = (const float*)d_in[8];
    const float* br = (const float*)d_in[9];
    const float* att = (const float*)d_in[10];
    const float* gbias = (const float*)d_in[11];
    const float* ln_g = (const float*)d_in[12];
    const float* ln_b = (const float*)d_in[13];
    const float* h1_W = (const float*)d_in[14];
    const float* h1_b = (const float*)d_in[15];
    const float* h2_W = (const float*)d_in[16];
    const float* h2_b = (const float*)d_in[17];
    float* out = (float*)d_out;

    int E = in_sizes[1] / 2;

    float *pX, *pTmp, *pXL, *pXR, *pcProj, *pcWl, *pcWr, *pcH1;
    cudaGetSymbolAddress((void**)&pX, g_X);
    cudaGetSymbolAddress((void**)&pTmp, g_tmp);
    cudaGetSymbolAddress((void**)&pXL, g_XL);
    cudaGetSymbolAddress((void**)&pXR, g_XR);
    cudaGetSymbolAddress((void**)&pcProj, g_cprojW);
    cudaGetSymbolAddress((void**)&pcWl, g_cWl);
    cudaGetSymbolAddress((void**)&pcWr, g_cWr);
    cudaGetSymbolAddress((void**)&pcH1, g_ch1W);

    cudaFuncSetAttribute(gemm_tc_kernel,
                         cudaFuncAttributeMaxDynamicSharedMemorySize, GEMM_SMEM);

    dim3 g1((Nn + 127) / 128, HIDc / 128, 1);
    dim3 g2((Nn + 127) / 128, HIDc / 128, 2);
    int nodeWarpBlocks = (Nn + 7) / 8;

    cudaStream_t s2;
    cudaStreamCreateWithFlags(&s2, cudaStreamNonBlocking);
    cudaEvent_t evFork, evJoin;
    cudaEventCreateWithFlags(&evFork, cudaEventDisableTiming);
    cudaEventCreateWithFlags(&evJoin, cudaEventDisableTiming);

    detect_idx_kernel<<<1, 32>>>(ei);
    // proj_W conversion needed immediately (before proj GEMM) on main stream
    cvt_w_kernel<<<(IN_DIMc * HIDc + 255) / 256, 256>>>(proj_W, pcProj, IN_DIMc * HIDc);
    cudaEventRecord(evFork, 0);
    cudaStreamWaitEvent(s2, evFork, 0);

    // side stream: remaining weight conversions + CSR build (hidden under proj GEMM)
    cvt_w_kernel<<<(HOPSc * HIDc * HIDc + 255) / 256, 256, 0, s2>>>(Wl, pcWl, HOPSc * HIDc * HIDc);
    cvt_w_kernel<<<(HOPSc * HIDc * HIDc + 255) / 256, 256, 0, s2>>>(Wr, pcWr, HOPSc * HIDc * HIDc);
    cvt_w_kernel<<<(HIDc * HIDc + 255) / 256, 256, 0, s2>>>(h1_W, pcH1, HIDc * HIDc);
    deg_zero_kernel<<<(Nn + 255) / 256, 256, 0, s2>>>();
    hist_kernel<<<(E + 255) / 256, 256, 0, s2>>>(ei, E);
    scan_kernel<<<1, 1024, 0, s2>>>();
    fill_kernel<<<(E + 255) / 256, 256, 0, s2>>>(ei, E);
    cudaEventRecord(evJoin, s2);

    // proj + input LN on main stream
    gemm_tc_kernel<<<g1, 256, GEMM_SMEM>>>(features, pcProj, pcProj, proj_b, proj_b,
                                           pTmp, pTmp, Nn, IN_DIMc, HIDc);
    ln_kernel<<<Nn, 256>>>(pTmp, n0_g, n0_b, pX);

    cudaStreamWaitEvent(0, evJoin, 0);

    for (int h = 0; h < HOPSc; h++) {
        const float* Wlh = pcWl + (size_t)h * HIDc * HIDc;
        const float* Wrh = pcWr + (size_t)h * HIDc * HIDc;
        gemm_tc_kernel<<<g2, 256, GEMM_SMEM>>>(pX, Wlh, Wrh, bl + h * HIDc, br + h * HIDc,
                                               pXL, pXR, Nn, HIDc, HIDc);
        edge_agg_kernel<<<nodeWarpBlocks, 256>>>(pXL, pXR, att + h * HEADSc * HDc,
                                                 gbias + h * HIDc,
                                                 ln_g + h * HIDc, ln_b + h * HIDc, pX);
    }

    // head
    gemm_tc_kernel<<<g1, 256, GEMM_SMEM>>>(pX, pcH1, pcH1, h1_b, h1_b,
                                           pTmp, pTmp, Nn, HIDc, HIDc);
    head2_kernel<<<(Nn + 7) / 8, 256>>>(pTmp, h2_W, h2_b, out);

    cudaEventDestroy(evFork);
    cudaEventDestroy(evJoin);
    cudaStreamDestroy(s2);
}

// round 15
// speedup vs baseline: 5.8788x; 1.0165x over previous
#include <cuda_runtime.h>
#include <math.h>
#include <stdint.h>

#define Nn 20000
#define IN_DIMc 1536
#define HIDc 256
#define HEADSc 4
#define HDc 64
#define HOPSc 3
#define NCLSc 3
#define EMAXc 400000
#define EPSV 1e-5f
#define NEG_SLOPE 0.2f

// ---------------- scratch (device globals; no allocations) ----------------
__device__ float g_X[Nn * HIDc];     // exact activations (residual path)
__device__ float g_Xr[Nn * HIDc];    // tf32-pre-rounded copy (GEMM A operand)
__device__ float g_tmp[Nn * HIDc];
__device__ float g_XL[Nn * HIDc];
__device__ float g_XR[Nn * HIDc];
__device__ int g_deg[Nn];
__device__ int g_rowptr[Nn + 1];
__device__ int g_cursor[Nn];
__device__ int g_esrc[EMAXc];
__device__ int g_flag;  // 1 = edge_index is int64, 0 = int32
// tf32-pre-rounded weights
__device__ float g_cprojW[IN_DIMc * HIDc];
__device__ float g_cWl[HOPSc * HIDc * HIDc];
__device__ float g_cWr[HOPSc * HIDc * HIDc];
__device__ float g_ch1W[HIDc * HIDc];

// ---------------- dtype probe ----------------
__global__ void detect_idx_kernel(const void* __restrict__ ei) {
    if (threadIdx.x == 0 && blockIdx.x == 0) {
        const long long* p = (const long long*)ei;
        int ok = 1;
        for (int i = 0; i < 256; i++) {
            long long v = p[i];
            if (v < 0 || v >= (long long)Nn) { ok = 0; break; }
        }
        g_flag = ok;
    }
}

__device__ __forceinline__ int edge_get(const void* ei, long long idx, int flag) {
    return flag ? (int)((const long long*)ei)[idx] : ((const int*)ei)[idx];
}

// ---------------- tf32 helpers ----------------
__device__ __forceinline__ uint32_t cvt_tf32(uint32_t bits) {
    float f = __uint_as_float(bits);
    uint32_t r;
    asm("cvt.rna.tf32.f32 %0, %1;" : "=r"(r) : "f"(f));
    return r;
}
__device__ __forceinline__ float round_tf32(float f) {
    return __uint_as_float(cvt_tf32(__float_as_uint(f)));
}

__global__ void cvt_w_kernel(const float* __restrict__ src, float* __restrict__ dst, int n) {
    int i = blockIdx.x * blockDim.x + threadIdx.x;
    if (i < n) dst[i] = round_tf32(src[i]);
}

// ---------------- CSR build ----------------
__global__ void deg_zero_kernel() {
    int i = blockIdx.x * blockDim.x + threadIdx.x;
    if (i < Nn) g_deg[i] = 0;
}

__global__ void hist_kernel(const void* __restrict__ ei, int E) {
    int e = blockIdx.x * blockDim.x + threadIdx.x;
    if (e >= E) return;
    int dst = edge_get(ei, (long long)E + e, g_flag);
    atomicAdd(&g_deg[dst], 1);
}

__global__ void scan_kernel() {
    const int PER = 20;
    __shared__ int wsum[32];
    __shared__ int wexcl[32];
    int tid = threadIdx.x, lane = tid & 31, wid = tid >> 5;
    int base = tid * PER;

    int deg[PER];
    int tot = 0;
#pragma unroll
    for (int i = 0; i < PER; i++) {
        int idx = base + i;
        deg[i] = (idx < Nn) ? g_deg[idx] : 0;
        tot += deg[i];
    }
    int incl = tot;
#pragma unroll
    for (int o = 1; o < 32; o <<= 1) {
        int t = __shfl_up_sync(0xffffffffu, incl, o);
        if (lane >= o) incl += t;
    }
    if (lane == 31) wsum[wid] = incl;
    __syncthreads();
    if (wid == 0) {
        int v = wsum[lane];
        int s = v;
#pragma unroll
        for (int o = 1; o < 32; o <<= 1) {
            int t = __shfl_up_sync(0xffffffffu, s, o);
            if (lane >= o) s += t;
        }
        wexcl[lane] = s - v;
    }
    __syncthreads();

    int running = wexcl[wid] + (incl - tot);
#pragma unroll
    for (int i = 0; i < PER; i++) {
        int idx = base + i;
        if (idx < Nn) {
            g_cursor[idx] = running;
            running += deg[i];
            g_rowptr[idx + 1] = running;
        }
    }
    if (tid == 0) g_rowptr[0] = 0;
}

__global__ void fill_kernel(const void* __restrict__ ei, int E) {
    int e = blockIdx.x * blockDim.x + threadIdx.x;
    if (e >= E) return;
    int flag = g_flag;
    int src = edge_get(ei, e, flag);
    int dst = edge_get(ei, (long long)E + e, flag);
    int pos = atomicAdd(&g_cursor[dst], 1);
    g_esrc[pos] = src;
}

// ---------------- TF32 tensor-core GEMM (BK=32, 2-stage cp.async) --------
// CVTA=true: round A fragments in-loop (A is raw fp32, e.g. features).
// CVTA=false: A already tf32-pre-rounded. B always pre-rounded.
__device__ __forceinline__ void mma_tf32(float* c, uint32_t a0, uint32_t a1,
                                         uint32_t a2, uint32_t a3,
                                         uint32_t b0, uint32_t b1) {
    asm volatile(
        "mma.sync.aligned.m16n8k8.row.col.f32.tf32.tf32.f32 "
        "{%0,%1,%2,%3}, {%4,%5,%6,%7}, {%8,%9}, {%0,%1,%2,%3};"
        : "+f"(c[0]), "+f"(c[1]), "+f"(c[2]), "+f"(c[3])
        : "r"(a0), "r"(a1), "r"(a2), "r"(a3), "r"(b0), "r"(b1));
}

__device__ __forceinline__ void cp16(uint32_t saddr, const float* gptr) {
    asm volatile("cp.async.ca.shared.global [%0], [%1], 16;" ::"r"(saddr), "l"(gptr));
}

#define BKc 32
#define ASTRIDE 36
#define BSTRIDE 136
#define AWORDS (128 * ASTRIDE)
#define BWORDS (BKc * BSTRIDE)
#define GEMM_SMEM (2 * (AWORDS + BWORDS) * 4)

template <bool CVTA>
__global__ __launch_bounds__(256, 2)
void gemm_tc_kernel(const float* __restrict__ A,
                    const float* __restrict__ B0, const float* __restrict__ B1,
                    const float* __restrict__ bias0, const float* __restrict__ bias1,
                    float* __restrict__ C0, float* __restrict__ C1,
                    int M, int K, int Nc) {
    const float* __restrict__ B = blockIdx.z ? B1 : B0;
    const float* __restrict__ bias = blockIdx.z ? bias1 : bias0;
    float* __restrict__ C = blockIdx.z ? C1 : C0;

    extern __shared__ __align__(16) uint32_t dyn[];
    uint32_t* Asm = dyn;
    uint32_t* Bsm = dyn + 2 * AWORDS;

    int tid = threadIdx.x;
    int rm = blockIdx.x * 128, cn = blockIdx.y * 128;

    int arow = tid >> 3, aq = (tid & 7) * 4;
    int bkr = tid >> 5, bq = (tid & 31) * 4;

    const float* ga[4];
    uint32_t sAa[2][4], sBa[2][4];
#pragma unroll
    for (int p = 0; p < 4; p++) {
        int r = arow + p * 32;
        ga[p] = A + (size_t)min(rm + r, M - 1) * K + aq;
#pragma unroll
        for (int s = 0; s < 2; s++)
            sAa[s][p] = (uint32_t)__cvta_generic_to_shared(Asm + s * AWORDS + r * ASTRIDE + aq);
    }
    const float* gb[4];
#pragma unroll
    for (int p = 0; p < 4; p++) {
        int kr = bkr + p * 8;
        gb[p] = B + (size_t)kr * Nc + cn + bq;
#pragma unroll
        for (int s = 0; s < 2; s++)
            sBa[s][p] = (uint32_t)__cvta_generic_to_shared(Bsm + s * BWORDS + kr * BSTRIDE + bq);
    }

    int warp = tid >> 5, lane = tid & 31, grp = lane >> 2, qid = lane & 3;
    int wm = (warp & 3) * 32, wn = (warp >> 2) * 64;

    float acc[2][8][4];
#pragma unroll
    for (int mt = 0; mt < 2; mt++)
#pragma unroll
        for (int nt = 0; nt < 8; nt++)
#pragma unroll
            for (int i = 0; i < 4; i++) acc[mt][nt][i] = 0.f;

    int ntile = K / BKc;

#pragma unroll
    for (int p = 0; p < 4; p++) {
        cp16(sAa[0][p], ga[p]);
        cp16(sBa[0][p], gb[p]);
    }
    asm volatile("cp.async.commit_group;");

    int s = 0;
    for (int t = 0; t < ntile; t++) {
        if (t + 1 < ntile) {
            int kt = (t + 1) * BKc;
#pragma unroll
            for (int p = 0; p < 4; p++) {
                cp16(sAa[s ^ 1][p], ga[p] + kt);
                cp16(sBa[s ^ 1][p], gb[p] + (size_t)kt * Nc);
            }
            asm volatile("cp.async.commit_group;");
            asm volatile("cp.async.wait_group 1;");
        } else {
            asm volatile("cp.async.wait_group 0;");
        }
        __syncthreads();

        const uint32_t* As = Asm + s * AWORDS;
        const uint32_t* Bs = Bsm + s * BWORDS;
#pragma unroll
        for (int ks = 0; ks < BKc; ks += 8) {
            uint32_t af[2][4];
#pragma unroll
            for (int mt = 0; mt < 2; mt++) {
                int m = wm + mt * 16 + grp;
                if (CVTA) {
                    af[mt][0] = cvt_tf32(As[m * ASTRIDE + ks + qid]);
                    af[mt][1] = cvt_tf32(As[(m + 8) * ASTRIDE + ks + qid]);
                    af[mt][2] = cvt_tf32(As[m * ASTRIDE + ks + qid + 4]);
                    af[mt][3] = cvt_tf32(As[(m + 8) * ASTRIDE + ks + qid + 4]);
                } else {
                    af[mt][0] = As[m * ASTRIDE + ks + qid];
                    af[mt][1] = As[(m + 8) * ASTRIDE + ks + qid];
                    af[mt][2] = As[m * ASTRIDE + ks + qid + 4];
                    af[mt][3] = As[(m + 8) * ASTRIDE + ks + qid + 4];
                }
            }
#pragma unroll
            for (int nt = 0; nt < 8; nt++) {
                int n = wn + nt * 8 + grp;
                uint32_t b0 = Bs[(ks + qid) * BSTRIDE + n];
                uint32_t b1 = Bs[(ks + qid + 4) * BSTRIDE + n];
                mma_tf32(acc[0][nt], af[0][0], af[0][1], af[0][2], af[0][3], b0, b1);
                mma_tf32(acc[1][nt], af[1][0], af[1][1], af[1][2], af[1][3], b0, b1);
            }
        }
        __syncthreads();
        s ^= 1;
    }

#pragma unroll
    for (int nt = 0; nt < 8; nt++) {
        int gcol = cn + wn + nt * 8 + qid * 2;
        float2 bb = *(const float2*)(bias + gcol);
#pragma unroll
        for (int mt = 0; mt < 2; mt++) {
            int r0 = rm + wm + mt * 16 + grp;
            int r1 = r0 + 8;
            if (r0 < M) {
                float2 o = make_float2(acc[mt][nt][0] + bb.x, acc[mt][nt][1] + bb.y);
                *(float2*)(C + (size_t)r0 * Nc + gcol) = o;
            }
            if (r1 < M) {
                float2 o = make_float2(acc[mt][nt][2] + bb.x, acc[mt][nt][3] + bb.y);
                *(float2*)(C + (size_t)r1 * Nc + gcol) = o;
            }
        }
    }
}

// ---------------- fused edge aggregation + bias/residual/LN --------------
// Warp per dst. Software-pipelined: src prefetched 2 edges ahead, xl row 1
// edge ahead, so the ~250cyc L2 gather overlaps the current edge's compute.
// Writes exact X (residual) and tf32-rounded Xr (next GEMM's A operand).
__global__ __launch_bounds__(256)
void edge_agg_kernel(const float* __restrict__ XL, const float* __restrict__ XR,
                     const float* __restrict__ att,
                     const float* __restrict__ gbias,
                     const float* __restrict__ lng, const float* __restrict__ lnb,
                     float* __restrict__ X, float* __restrict__ Xr) {
    int n = blockIdx.x * 8 + (threadIdx.x >> 5);
    if (n >= Nn) return;
    int lane = threadIdx.x & 31;

    const float4* xr4 = (const float4*)(XR + (size_t)n * HIDc) + lane * 2;
    const float4* at4 = (const float4*)att + lane * 2;
    float4 xr0 = xr4[0], xr1 = xr4[1];
    float4 at0 = at4[0], at1 = at4[1];

    float m = -1e30f, d = 0.f;
    float acc[8];
#pragma unroll
    for (int j = 0; j < 8; j++) acc[j] = 0.f;

    int beg = g_rowptr[n], end = g_rowptr[n + 1];
    int nE = end - beg;  // real in-edges; self loop appended at i == nE

    // prologue: src(0), src(1), xl row for edge 0
    int sn1 = (0 < nE) ? __ldg(g_esrc + beg) : n;      // src(i+0) at entry
    int sn2 = (1 < nE) ? __ldg(g_esrc + beg + 1) : n;  // src(i+1)
    const float4* p0 = (const float4*)(XL + (size_t)sn1 * HIDc) + lane * 2;
    float4 ca0 = p0[0], ca1 = p0[1];

    for (int i = 0; i <= nE; i++) {
        float4 a0 = ca0, a1 = ca1;  // current edge's xl
        // prefetch next edge's xl row (from sn2 = src(i+1))
        if (i < nE) {
            const float4* q = (const float4*)(XL + (size_t)sn2 * HIDc) + lane * 2;
            ca0 = q[0];
            ca1 = q[1];
        }
        // prefetch src(i+2)
        sn2 = (i + 2 < nE) ? __ldg(g_esrc + beg + i + 2) : n;

        float s, v;
        v = a0.x + xr0.x; v = fmaxf(v, NEG_SLOPE * v); s  = v * at0.x;
        v = a0.y + xr0.y; v = fmaxf(v, NEG_SLOPE * v); s += v * at0.y;
        v = a0.z + xr0.z; v = fmaxf(v, NEG_SLOPE * v); s += v * at0.z;
        v = a0.w + xr0.w; v = fmaxf(v, NEG_SLOPE * v); s += v * at0.w;
        v = a1.x + xr1.x; v = fmaxf(v, NEG_SLOPE * v); s += v * at1.x;
        v = a1.y + xr1.y; v = fmaxf(v, NEG_SLOPE * v); s += v * at1.y;
        v = a1.z + xr1.z; v = fmaxf(v, NEG_SLOPE * v); s += v * at1.z;
        v = a1.w + xr1.w; v = fmaxf(v, NEG_SLOPE * v); s += v * at1.w;
        s += __shfl_xor_sync(0xffffffffu, s, 1);
        s += __shfl_xor_sync(0xffffffffu, s, 2);
        s += __shfl_xor_sync(0xffffffffu, s, 4);

        float nm = fmaxf(m, s);
        float sc = __expf(m - nm);
        float w = __expf(s - nm);
        d = d * sc + w;
        acc[0] = acc[0] * sc + w * a0.x;
        acc[1] = acc[1] * sc + w * a0.y;
        acc[2] = acc[2] * sc + w * a0.z;
        acc[3] = acc[3] * sc + w * a0.w;
        acc[4] = acc[4] * sc + w * a1.x;
        acc[5] = acc[5] * sc + w * a1.y;
        acc[6] = acc[6] * sc + w * a1.z;
        acc[7] = acc[7] * sc + w * a1.w;
        m = nm;
    }

    float inv = 1.f / d;
    float4* xrow = (float4*)(X + (size_t)n * HIDc) + lane * 2;
    float4 x0 = xrow[0], x1 = xrow[1];
    const float4* gb4 = (const float4*)gbias + lane * 2;
    float4 gb0 = gb4[0], gb1 = gb4[1];
    float v[8];
    v[0] = acc[0] * inv + gb0.x + x0.x;
    v[1] = acc[1] * inv + gb0.y + x0.y;
    v[2] = acc[2] * inv + gb0.z + x0.z;
    v[3] = acc[3] * inv + gb0.w + x0.w;
    v[4] = acc[4] * inv + gb1.x + x1.x;
    v[5] = acc[5] * inv + gb1.y + x1.y;
    v[6] = acc[6] * inv + gb1.z + x1.z;
    v[7] = acc[7] * inv + gb1.w + x1.w;

    float s = 0.f, sq = 0.f;
#pragma unroll
    for (int j = 0; j < 8; j++) { s += v[j]; sq += v[j] * v[j]; }
#pragma unroll
    for (int o = 16; o > 0; o >>= 1) {
        s += __shfl_xor_sync(0xffffffffu, s, o);
        sq += __shfl_xor_sync(0xffffffffu, sq, o);
    }
    float mu = s * (1.f / HIDc);
    float var = sq * (1.f / HIDc) - mu * mu;
    float rs = rsqrtf(var + EPSV);

    const float4* lg4 = (const float4*)lng + lane * 2;
    const float4* lb4 = (const float4*)lnb + lane * 2;
    float4 lg0 = lg4[0], lg1 = lg4[1];
    float4 lb0 = lb4[0], lb1 = lb4[1];
    float4 o0, o1;
    o0.x = (v[0] - mu) * rs * lg0.x + lb0.x;
    o0.y = (v[1] - mu) * rs * lg0.y + lb0.y;
    o0.z = (v[2] - mu) * rs * lg0.z + lb0.z;
    o0.w = (v[3] - mu) * rs * lg0.w + lb0.w;
    o1.x = (v[4] - mu) * rs * lg1.x + lb1.x;
    o1.y = (v[5] - mu) * rs * lg1.y + lb1.y;
    o1.z = (v[6] - mu) * rs * lg1.z + lb1.z;
    o1.w = (v[7] - mu) * rs * lg1.w + lb1.w;
    xrow[0] = o0;
    xrow[1] = o1;

    float4* xrr = (float4*)(Xr + (size_t)n * HIDc) + lane * 2;
    float4 r0, r1;
    r0.x = round_tf32(o0.x); r0.y = round_tf32(o0.y);
    r0.z = round_tf32(o0.z); r0.w = round_tf32(o0.w);
    r1.x = round_tf32(o1.x); r1.y = round_tf32(o1.y);
    r1.z = round_tf32(o1.z); r1.w = round_tf32(o1.w);
    xrr[0] = r0;
    xrr[1] = r1;
}

// ---------------- input LN (once, after proj); dual exact/rounded out ----
__device__ __forceinline__ void block_mean_var_256(float v, float* smem, float& mu, float& var) {
    float s = v, sq = v * v;
#pragma unroll
    for (int o = 16; o > 0; o >>= 1) {
        s += __shfl_xor_sync(0xffffffffu, s, o);
        sq += __shfl_xor_sync(0xffffffffu, sq, o);
    }
    int w = threadIdx.x >> 5, l = threadIdx.x & 31;
    if (l == 0) { smem[w] = s; smem[8 + w] = sq; }
    __syncthreads();
    if (w == 0) {
        s = (l < 8) ? smem[l] : 0.f;
        sq = (l < 8) ? smem[8 + l] : 0.f;
#pragma unroll
        for (int o = 4; o > 0; o >>= 1) {
            s += __shfl_xor_sync(0xffffffffu, s, o);
            sq += __shfl_xor_sync(0xffffffffu, sq, o);
        }
        if (l == 0) { smem[0] = s; smem[8] = sq; }
    }
    __syncthreads();
    mu = smem[0] * (1.f / HIDc);
    var = smem[8] * (1.f / HIDc) - mu * mu;
}

__global__ void ln_kernel(const float* __restrict__ in, const float* __restrict__ g,
                          const float* __restrict__ b, float* __restrict__ out,
                          float* __restrict__ outr) {
    __shared__ float smem[16];
    int n = blockIdx.x, c = threadIdx.x;
    float v = in[(size_t)n * HIDc + c];
    float mu, var;
    block_mean_var_256(v, smem, mu, var);
    float o = (v - mu) * rsqrtf(var + EPSV) * g[c] + b[c];
    out[(size_t)n * HIDc + c] = o;
    outr[(size_t)n * HIDc + c] = round_tf32(o);
}

// ---------------- head: GELU(T) @ h2_W + h2_b, warp per node -------------
__global__ void head2_kernel(const float* __restrict__ T, const float* __restrict__ W2,
                             const float* __restrict__ b2, float* __restrict__ out) {
    int n = blockIdx.x * 8 + (threadIdx.x >> 5);
    if (n >= Nn) return;
    int lane = threadIdx.x & 31;
    const float* t = T + (size_t)n * HIDc;
    float a0 = 0.f, a1 = 0.f, a2 = 0.f;
#pragma unroll
    for (int j = 0; j < 8; j++) {
        int k = j * 32 + lane;
        float x = t[k];
        float ge = 0.5f * x * (1.f + erff(x * 0.70710678118654752440f));
        a0 += ge * W2[k * 3 + 0];
        a1 += ge * W2[k * 3 + 1];
        a2 += ge * W2[k * 3 + 2];
    }
#pragma unroll
    for (int o = 16; o > 0; o >>= 1) {
        a0 += __shfl_xor_sync(0xffffffffu, a0, o);
        a1 += __shfl_xor_sync(0xffffffffu, a1, o);
        a2 += __shfl_xor_sync(0xffffffffu, a2, o);
    }
    if (lane == 0) {
        out[n * 3 + 0] = a0 + b2[0];
        out[n * 3 + 1] = a1 + b2[1];
        out[n * 3 + 2] = a2 + b2[2];
    }
}

// ---------------- launcher ----------------
extern "C" void kernel_launch(void* const* d_in, const int* in_sizes, int n_in,
                              void* d_out, int out_size) {
    const float* features = (const float*)d_in[0];
    const void* ei = d_in[1];
    const float* proj_W = (const float*)d_in[2];
    const float* proj_b = (const float*)d_in[3];
    const float* n0_g = (const float*)d_in[4];
    const float* n0_b = (const float*)d_in[5];
    const float* Wl = (const float*)d_in[6];
    const float* bl = (const float*)d_in[7];
    const float* Wr = (const float*)d_in[8];
    const float* br = (const float*)d_in[9];
    const float* att = (const float*)d_in[10];
    const float* gbias = (const float*)d_in[11];
    const float* ln_g = (const float*)d_in[12];
    const float* ln_b = (const float*)d_in[13];
    const float* h1_W = (const float*)d_in[14];
    const float* h1_b = (const float*)d_in[15];
    const float* h2_W = (const float*)d_in[16];
    const float* h2_b = (const float*)d_in[17];
    float* out = (float*)d_out;

    int E = in_sizes[1] / 2;

    float *pX, *pXr, *pTmp, *pXL, *pXR, *pcProj, *pcWl, *pcWr, *pcH1;
    cudaGetSymbolAddress((void**)&pX, g_X);
    cudaGetSymbolAddress((void**)&pXr, g_Xr);
    cudaGetSymbolAddress((void**)&pTmp, g_tmp);
    cudaGetSymbolAddress((void**)&pXL, g_XL);
    cudaGetSymbolAddress((void**)&pXR, g_XR);
    cudaGetSymbolAddress((void**)&pcProj, g_cprojW);
    cudaGetSymbolAddress((void**)&pcWl, g_cWl);
    cudaGetSymbolAddress((void**)&pcWr, g_cWr);
    cudaGetSymbolAddress((void**)&pcH1, g_ch1W);

    cudaFuncSetAttribute(gemm_tc_kernel<true>,
                         cudaFuncAttributeMaxDynamicSharedMemorySize, GEMM_SMEM);
    cudaFuncSetAttribute(gemm_tc_kernel<false>,
                         cudaFuncAttributeMaxDynamicSharedMemorySize, GEMM_SMEM);

    dim3 g1((Nn + 127) / 128, HIDc / 128, 1);
    dim3 g2((Nn + 127) / 128, HIDc / 128, 2);
    int nodeWarpBlocks = (Nn + 7) / 8;

    cudaStream_t s2;
    cudaStreamCreateWithFlags(&s2, cudaStreamNonBlocking);
    cudaEvent_t evFork, evJoin;
    cudaEventCreateWithFlags(&evFork, cudaEventDisableTiming);
    cudaEventCreateWithFlags(&evJoin, cudaEventDisableTiming);

    detect_idx_kernel<<<1, 32>>>(ei);
    cvt_w_kernel<<<(IN_DIMc * HIDc + 255) / 256, 256>>>(proj_W, pcProj, IN_DIMc * HIDc);
    cudaEventRecord(evFork, 0);
    cudaStreamWaitEvent(s2, evFork, 0);

    cvt_w_kernel<<<(HOPSc * HIDc * HIDc + 255) / 256, 256, 0, s2>>>(Wl, pcWl, HOPSc * HIDc * HIDc);
    cvt_w_kernel<<<(HOPSc * HIDc * HIDc + 255) / 256, 256, 0, s2>>>(Wr, pcWr, HOPSc * HIDc * HIDc);
    cvt_w_kernel<<<(HIDc * HIDc + 255) / 256, 256, 0, s2>>>(h1_W, pcH1, HIDc * HIDc);
    deg_zero_kernel<<<(Nn + 255) / 256, 256, 0, s2>>>();
    hist_kernel<<<(E + 255) / 256, 256, 0, s2>>>(ei, E);
    scan_kernel<<<1, 1024, 0, s2>>>();
    fill_kernel<<<(E + 255) / 256, 256, 0, s2>>>(ei, E);
    cudaEventRecord(evJoin, s2);

    gemm_tc_kernel<true><<<g1, 256, GEMM_SMEM>>>(features, pcProj, pcProj, proj_b, proj_b,
                                                 pTmp, pTmp, Nn, IN_DIMc, HIDc);
    ln_kernel<<<Nn, 256>>>(pTmp, n0_g, n0_b, pX, pXr);

    cudaStreamWaitEvent(0, evJoin, 0);

    for (int h = 0; h < HOPSc; h++) {
        const float* Wlh = pcWl + (size_t)h * HIDc * HIDc;
        const float* Wrh = pcWr + (size_t)h * HIDc * HIDc;
        gemm_tc_kernel<false><<<g2, 256, GEMM_SMEM>>>(pXr, Wlh, Wrh, bl + h * HIDc, br + h * HIDc,
                                                      pXL, pXR, Nn, HIDc, HIDc);
        edge_agg_kernel<<<nodeWarpBlocks, 256>>>(pXL, pXR, att + h * HEADSc * HDc,
                                                 gbias + h * HIDc,
                                                 ln_g + h * HIDc, ln_b + h * HIDc, pX, pXr);
    }

    gemm_tc_kernel<false><<<g1, 256, GEMM_SMEM>>>(pXr, pcH1, pcH1, h1_b, h1_b,
                                                  pTmp, pTmp, Nn, HIDc, HIDc);
    head2_kernel<<<(Nn + 7) / 8, 256>>>(pTmp, h2_W, h2_b, out);

    cudaEventDestroy(evFork);
    cudaEventDestroy(evJoin);
    cudaStreamDestroy(s2);
}